// round 1
// baseline (speedup 1.0000x reference)
#include <cuda_runtime.h>
#include <math.h>
#include <stdint.h>

#define Bsz 4
#define Tlen 1024
#define Dm 768
#define Nh 12
#define HDm 64
#define Fm 3072
#define Lc 12
#define Vv 50257
#define Rows (Bsz*Tlen)   /* 4096 */

// ---------------- scratch (static device globals; no allocation) ----------------
__device__ float g_x[Rows*Dm];        // residual stream
__device__ float g_h[Rows*Dm];        // layernorm output
__device__ float g_qkv[Rows*3*Dm];    // qkv
__device__ float g_attn[Rows*Dm];     // attention output (pre-proj)
__device__ float g_fc[Rows*Fm];       // mlp hidden

// ---------------- embedding ----------------
__global__ void embed_kernel(const int* __restrict__ tokens,
                             const float* __restrict__ wte,
                             const float* __restrict__ wpe,
                             float* __restrict__ x) {
    int row = blockIdx.x;                 // b*T + t
    int t   = row % Tlen;
    int tok = tokens[row];
    const float* we = wte + (size_t)tok * Dm;
    const float* pe = wpe + (size_t)t   * Dm;
    float* xr = x + (size_t)row * Dm;
    for (int i = threadIdx.x; i < Dm; i += blockDim.x)
        xr[i] = we[i] + pe[i];
}

// ---------------- layernorm (one block / row, 256 threads, D=768=3*256) ----------------
__global__ void ln_kernel(const float* __restrict__ x,
                          const float* __restrict__ g,
                          const float* __restrict__ b,
                          float* __restrict__ o) {
    int row = blockIdx.x;
    int tid = threadIdx.x;
    const float* xr = x + (size_t)row * Dm;
    float v0 = xr[tid], v1 = xr[tid + 256], v2 = xr[tid + 512];
    __shared__ float red[256];
    red[tid] = v0 + v1 + v2;
    __syncthreads();
    #pragma unroll
    for (int s = 128; s > 0; s >>= 1) {
        if (tid < s) red[tid] += red[tid + s];
        __syncthreads();
    }
    float mean = red[0] * (1.0f / Dm);
    __syncthreads();
    float d0 = v0 - mean, d1 = v1 - mean, d2 = v2 - mean;
    red[tid] = d0 * d0 + d1 * d1 + d2 * d2;
    __syncthreads();
    #pragma unroll
    for (int s = 128; s > 0; s >>= 1) {
        if (tid < s) red[tid] += red[tid + s];
        __syncthreads();
    }
    float rstd = rsqrtf(red[0] * (1.0f / Dm) + 1e-5f);
    float* orow = o + (size_t)row * Dm;
    orow[tid]       = d0 * rstd * g[tid]       + b[tid];
    orow[tid + 256] = d1 * rstd * g[tid + 256] + b[tid + 256];
    orow[tid + 512] = d2 * rstd * g[tid + 512] + b[tid + 512];
}

// ---------------- SGEMM: C[M,N] = A[M,K] @ B + bias (+res) (gelu) ----------------
// BT=false: B is [K,N] row-major.   BT=true: B is [N,K] row-major (lm_head / wte).
// 64x64x16 tile, 256 threads, 4x4 microtile.
template<int ACT, bool BT, bool RES, bool BIAS>
__global__ void gemm_kernel(const float* __restrict__ A, const float* __restrict__ B,
                            const float* __restrict__ bias, const float* __restrict__ res,
                            float* __restrict__ C, int M, int N, int K) {
    __shared__ float As[16][68];
    __shared__ float Bs[16][68];
    int tid = threadIdx.x;
    int tx = tid & 15, ty = tid >> 4;
    int bx = blockIdx.x, by = blockIdx.y;
    float acc[4][4] = {};

    for (int k0 = 0; k0 < K; k0 += 16) {
        { // A tile: 64 rows x 16 k  (K always multiple of 16, M multiple of 64)
            int r  = tid >> 2;
            int kk = (tid & 3) << 2;
            float4 av = *(const float4*)(A + (size_t)(by * 64 + r) * K + k0 + kk);
            As[kk + 0][r] = av.x; As[kk + 1][r] = av.y;
            As[kk + 2][r] = av.z; As[kk + 3][r] = av.w;
        }
        if (BT) { // B[N,K]: load along K (coalesced), transpose into Bs
            int c  = tid >> 2;
            int kk = (tid & 3) << 2;
            int col = bx * 64 + c;
            float4 bv = make_float4(0.f, 0.f, 0.f, 0.f);
            if (col < N) bv = *(const float4*)(B + (size_t)col * K + k0 + kk);
            Bs[kk + 0][c] = bv.x; Bs[kk + 1][c] = bv.y;
            Bs[kk + 2][c] = bv.z; Bs[kk + 3][c] = bv.w;
        } else {  // B[K,N]: 16 k-rows x 64 cols
            int r = tid >> 4;
            int c = (tid & 15) << 2;
            int col = bx * 64 + c;
            const float* bp = B + (size_t)(k0 + r) * N;
            float4 bv;
            if (col + 3 < N) bv = *(const float4*)(bp + col);
            else {
                bv.x = (col     < N) ? bp[col]     : 0.f;
                bv.y = (col + 1 < N) ? bp[col + 1] : 0.f;
                bv.z = (col + 2 < N) ? bp[col + 2] : 0.f;
                bv.w = (col + 3 < N) ? bp[col + 3] : 0.f;
            }
            *(float4*)&Bs[r][c] = bv;
        }
        __syncthreads();
        #pragma unroll
        for (int kk = 0; kk < 16; kk++) {
            float4 a  = *(const float4*)&As[kk][ty << 2];
            float4 bb = *(const float4*)&Bs[kk][tx << 2];
            acc[0][0] += a.x * bb.x; acc[0][1] += a.x * bb.y; acc[0][2] += a.x * bb.z; acc[0][3] += a.x * bb.w;
            acc[1][0] += a.y * bb.x; acc[1][1] += a.y * bb.y; acc[1][2] += a.y * bb.z; acc[1][3] += a.y * bb.w;
            acc[2][0] += a.z * bb.x; acc[2][1] += a.z * bb.y; acc[2][2] += a.z * bb.z; acc[2][3] += a.z * bb.w;
            acc[3][0] += a.w * bb.x; acc[3][1] += a.w * bb.y; acc[3][2] += a.w * bb.z; acc[3][3] += a.w * bb.w;
        }
        __syncthreads();
    }

    #pragma unroll
    for (int i = 0; i < 4; i++) {
        int m = by * 64 + (ty << 2) + i;
        #pragma unroll
        for (int j = 0; j < 4; j++) {
            int n = bx * 64 + (tx << 2) + j;
            if (n < N) {
                float v = acc[i][j];
                if (BIAS) v += bias[n];
                if (RES)  v += res[(size_t)m * N + n];
                if (ACT == 1) v *= normcdff(v);   // exact gelu: x * Phi(x)
                C[(size_t)m * N + n] = v;
            }
        }
    }
}

// ---------------- attention: 4 queries / block, 128 threads ----------------
// qkv layout per token: [q(768) | k(768) | v(768)], head n at offset n*64.
__global__ void attn_kernel(const float* __restrict__ qkv, float* __restrict__ out) {
    const int q0  = blockIdx.x * 4;
    const int n   = blockIdx.y;
    const int b   = blockIdx.z;
    const int tid = threadIdx.x;   // 128
    __shared__ float qs[4][64];
    __shared__ float sc[4][Tlen];
    __shared__ float red[128];
    __shared__ float mxs[4], sms[4];
    __shared__ float part[2][4][64];

    const float* base = qkv + (size_t)b * Tlen * (3 * Dm);

    // load 4 q-vectors
    for (int i = tid; i < 256; i += 128) {
        int qq = i >> 6, d = i & 63;
        qs[qq][d] = base[(size_t)(q0 + qq) * (3 * Dm) + n * 64 + d];
    }
    __syncthreads();

    const int kmax = q0 + 3;   // inclusive

    // phase 1: scores (thread-per-key, strided), causal masked
    float lm[4] = { -1e30f, -1e30f, -1e30f, -1e30f };
    for (int k = tid; k <= kmax; k += 128) {
        const float* kr = base + (size_t)k * (3 * Dm) + Dm + n * 64;
        float s[4] = {0.f, 0.f, 0.f, 0.f};
        #pragma unroll
        for (int d = 0; d < 64; d += 4) {
            float4 kv = *(const float4*)(kr + d);
            #pragma unroll
            for (int qq = 0; qq < 4; qq++)
                s[qq] += kv.x * qs[qq][d] + kv.y * qs[qq][d + 1]
                       + kv.z * qs[qq][d + 2] + kv.w * qs[qq][d + 3];
        }
        #pragma unroll
        for (int qq = 0; qq < 4; qq++) {
            float sv = (k <= q0 + qq) ? s[qq] * 0.125f : -1e30f;
            sc[qq][k] = sv;
            lm[qq] = fmaxf(lm[qq], sv);
        }
    }
    // block-reduce maxes
    for (int qq = 0; qq < 4; qq++) {
        red[tid] = lm[qq];
        __syncthreads();
        #pragma unroll
        for (int s = 64; s > 0; s >>= 1) {
            if (tid < s) red[tid] = fmaxf(red[tid], red[tid + s]);
            __syncthreads();
        }
        if (tid == 0) mxs[qq] = red[0];
        __syncthreads();
    }

    // phase 2: exp + sum
    float ls[4] = {0.f, 0.f, 0.f, 0.f};
    for (int k = tid; k <= kmax; k += 128) {
        #pragma unroll
        for (int qq = 0; qq < 4; qq++) {
            float e = expf(sc[qq][k] - mxs[qq]);
            sc[qq][k] = e;
            ls[qq] += e;
        }
    }
    for (int qq = 0; qq < 4; qq++) {
        red[tid] = ls[qq];
        __syncthreads();
        #pragma unroll
        for (int s = 64; s > 0; s >>= 1) {
            if (tid < s) red[tid] += red[tid + s];
            __syncthreads();
        }
        if (tid == 0) sms[qq] = red[0];
        __syncthreads();
    }

    // phase 3: o[d] = sum_k p_k * v[k][d]   (thread = (half,d), 2 halves over k)
    {
        int d = tid & 63, h = tid >> 6;
        float a[4] = {0.f, 0.f, 0.f, 0.f};
        for (int k = h; k <= kmax; k += 2) {
            float vv = base[(size_t)k * (3 * Dm) + 2 * Dm + n * 64 + d];
            #pragma unroll
            for (int qq = 0; qq < 4; qq++) a[qq] += sc[qq][k] * vv;
        }
        #pragma unroll
        for (int qq = 0; qq < 4; qq++) part[h][qq][d] = a[qq];
        __syncthreads();
        if (h == 0) {
            #pragma unroll
            for (int qq = 0; qq < 4; qq++) {
                float o = (part[0][qq][d] + part[1][qq][d]) / sms[qq];
                out[(size_t)(b * Tlen + q0 + qq) * Dm + n * 64 + d] = o;
            }
        }
    }
}

// ---------------- host driver ----------------
extern "C" void kernel_launch(void* const* d_in, const int* in_sizes, int n_in,
                              void* d_out, int out_size) {
    const int*   tokens      = (const int*)  d_in[0];
    const float* wte         = (const float*)d_in[1];
    const float* wpe         = (const float*)d_in[2];
    const float* ln1_g       = (const float*)d_in[3];
    const float* ln1_b       = (const float*)d_in[4];
    const float* attn_w      = (const float*)d_in[5];
    const float* attn_b      = (const float*)d_in[6];
    const float* attn_proj_w = (const float*)d_in[7];
    const float* attn_proj_b = (const float*)d_in[8];
    const float* ln2_g       = (const float*)d_in[9];
    const float* ln2_b       = (const float*)d_in[10];
    const float* fc_w        = (const float*)d_in[11];
    const float* fc_b        = (const float*)d_in[12];
    const float* mlp_proj_w  = (const float*)d_in[13];
    const float* mlp_proj_b  = (const float*)d_in[14];
    const float* lnf_g       = (const float*)d_in[15];
    const float* lnf_b       = (const float*)d_in[16];
    float* out = (float*)d_out;

    float *xp, *hp, *qkvp, *attnp, *fcp;
    cudaGetSymbolAddress((void**)&xp,    g_x);
    cudaGetSymbolAddress((void**)&hp,    g_h);
    cudaGetSymbolAddress((void**)&qkvp,  g_qkv);
    cudaGetSymbolAddress((void**)&attnp, g_attn);
    cudaGetSymbolAddress((void**)&fcp,   g_fc);

    embed_kernel<<<Rows, 256>>>(tokens, wte, wpe, xp);

    const dim3 gQKV(3 * Dm / 64, Rows / 64);
    const dim3 gD  (Dm / 64,     Rows / 64);
    const dim3 gF  (Fm / 64,     Rows / 64);
    const dim3 gV  ((Vv + 63) / 64, Rows / 64);
    const dim3 gAtt(Tlen / 4, Nh, Bsz);

    for (int l = 0; l < Lc; l++) {
        ln_kernel<<<Rows, 256>>>(xp, ln1_g + l * Dm, ln1_b + l * Dm, hp);
        gemm_kernel<0, false, false, true><<<gQKV, 256>>>(
            hp, attn_w + (size_t)l * Dm * 3 * Dm, attn_b + (size_t)l * 3 * Dm,
            nullptr, qkvp, Rows, 3 * Dm, Dm);
        attn_kernel<<<gAtt, 128>>>(qkvp, attnp);
        gemm_kernel<0, false, true, true><<<gD, 256>>>(
            attnp, attn_proj_w + (size_t)l * Dm * Dm, attn_proj_b + (size_t)l * Dm,
            xp, xp, Rows, Dm, Dm);
        ln_kernel<<<Rows, 256>>>(xp, ln2_g + l * Dm, ln2_b + l * Dm, hp);
        gemm_kernel<1, false, false, true><<<gF, 256>>>(
            hp, fc_w + (size_t)l * Dm * Fm, fc_b + (size_t)l * Fm,
            nullptr, fcp, Rows, Fm, Dm);
        gemm_kernel<0, false, true, true><<<gD, 256>>>(
            fcp, mlp_proj_w + (size_t)l * Fm * Dm, mlp_proj_b + (size_t)l * Dm,
            xp, xp, Rows, Dm, Fm);
    }

    ln_kernel<<<Rows, 256>>>(xp, lnf_g, lnf_b, hp);
    gemm_kernel<0, true, false, false><<<gV, 256>>>(
        hp, wte, nullptr, nullptr, out, Rows, Vv, Dm);
}

// round 3
// speedup vs baseline: 1.9141x; 1.9141x over previous
#include <cuda_runtime.h>
#include <cuda_bf16.h>
#include <math.h>
#include <stdint.h>

#define Bsz 4
#define Tlen 1024
#define Dm 768
#define Nh 12
#define Fm 3072
#define Lc 12
#define Vv 50257
#define Rows (Bsz*Tlen)   /* 4096 */

// ---------------- scratch (static device globals; no allocation) ----------------
__device__ float g_x[Rows*Dm];                             // residual stream (fp32)
__device__ __nv_bfloat16 g_hhi[Rows*Dm], g_hlo[Rows*Dm];   // LN output hi/lo
__device__ float g_qkv[Rows*3*Dm];
__device__ __nv_bfloat16 g_ahi[Rows*Dm], g_alo[Rows*Dm];   // attn out hi/lo
__device__ __nv_bfloat16 g_fchi[Rows*Fm], g_fclo[Rows*Fm]; // gelu(fc) hi/lo
// transposed + split weights [N,K]
__device__ __nv_bfloat16 w_qkv_hi[Lc*3*Dm*Dm], w_qkv_lo[Lc*3*Dm*Dm];
__device__ __nv_bfloat16 w_ap_hi [Lc*Dm*Dm],   w_ap_lo [Lc*Dm*Dm];
__device__ __nv_bfloat16 w_fc_hi [Lc*Fm*Dm],   w_fc_lo [Lc*Fm*Dm];
__device__ __nv_bfloat16 w_mp_hi [Lc*Dm*Fm],   w_mp_lo [Lc*Dm*Fm];
__device__ __nv_bfloat16 w_te_hi [Vv*Dm],      w_te_lo [Vv*Dm];

// ---------------- helpers ----------------
__device__ __forceinline__ uint32_t smem_u32(const void* p) {
    uint32_t a;
    asm("{ .reg .u64 t; cvta.to.shared.u64 t, %1; cvt.u32.u64 %0, t; }" : "=r"(a) : "l"(p));
    return a;
}
#define SWZ(o) ((o) ^ ((((uint32_t)(o)) >> 3) & 0x70))

__device__ __forceinline__ void cpasync16(uint32_t s, const void* g, uint32_t sz) {
    asm volatile("cp.async.cg.shared.global [%0], [%1], 16, %2;\n"
                 :: "r"(s), "l"(g), "r"(sz) : "memory");
}
__device__ __forceinline__ void cp_commit() {
    asm volatile("cp.async.commit_group;\n" ::: "memory");
}
__device__ __forceinline__ void cp_wait1() {
    asm volatile("cp.async.wait_group 1;\n" ::: "memory");
}
__device__ __forceinline__ void cp_wait0() {
    asm volatile("cp.async.wait_group 0;\n" ::: "memory");
}
__device__ __forceinline__ void ldsm4(uint32_t r[4], uint32_t addr) {
    asm volatile("ldmatrix.sync.aligned.m8n8.x4.shared.b16 {%0,%1,%2,%3}, [%4];"
                 : "=r"(r[0]), "=r"(r[1]), "=r"(r[2]), "=r"(r[3]) : "r"(addr));
}
__device__ __forceinline__ void mma16816(float c[4], const uint32_t a[4], const uint32_t b[2]) {
    asm volatile("mma.sync.aligned.m16n8k16.row.col.f32.bf16.bf16.f32 "
                 "{%0,%1,%2,%3}, {%4,%5,%6,%7}, {%8,%9}, {%0,%1,%2,%3};"
                 : "+f"(c[0]), "+f"(c[1]), "+f"(c[2]), "+f"(c[3])
                 : "r"(a[0]), "r"(a[1]), "r"(a[2]), "r"(a[3]), "r"(b[0]), "r"(b[1]));
}

// ---------------- embedding ----------------
__global__ void embed_kernel(const int* __restrict__ tokens,
                             const float* __restrict__ wte,
                             const float* __restrict__ wpe,
                             float* __restrict__ x) {
    int row = blockIdx.x;
    int t   = row % Tlen;
    int tok = tokens[row];
    const float* we = wte + (size_t)tok * Dm;
    const float* pe = wpe + (size_t)t   * Dm;
    float* xr = x + (size_t)row * Dm;
    for (int i = threadIdx.x; i < Dm; i += blockDim.x)
        xr[i] = we[i] + pe[i];
}

// ---------------- layernorm -> bf16 hi/lo ----------------
__global__ void ln_kernel(const float* __restrict__ x,
                          const float* __restrict__ g,
                          const float* __restrict__ b,
                          __nv_bfloat16* __restrict__ ohi,
                          __nv_bfloat16* __restrict__ olo) {
    int row = blockIdx.x;
    int tid = threadIdx.x;
    const float* xr = x + (size_t)row * Dm;
    float v0 = xr[tid], v1 = xr[tid + 256], v2 = xr[tid + 512];
    __shared__ float red[256];
    red[tid] = v0 + v1 + v2;
    __syncthreads();
    #pragma unroll
    for (int s = 128; s > 0; s >>= 1) { if (tid < s) red[tid] += red[tid + s]; __syncthreads(); }
    float mean = red[0] * (1.0f / Dm);
    __syncthreads();
    float d0 = v0 - mean, d1 = v1 - mean, d2 = v2 - mean;
    red[tid] = d0 * d0 + d1 * d1 + d2 * d2;
    __syncthreads();
    #pragma unroll
    for (int s = 128; s > 0; s >>= 1) { if (tid < s) red[tid] += red[tid + s]; __syncthreads(); }
    float rstd = rsqrtf(red[0] * (1.0f / Dm) + 1e-5f);
    size_t base = (size_t)row * Dm;
    #pragma unroll
    for (int j = 0; j < 3; j++) {
        int i = tid + j * 256;
        float dd = (j == 0) ? d0 : (j == 1) ? d1 : d2;
        float v = dd * rstd * g[i] + b[i];
        __nv_bfloat16 h = __float2bfloat16(v);
        ohi[base + i] = h;
        olo[base + i] = __float2bfloat16(v - __bfloat162float(h));
    }
}

// ---------------- weight transpose + hi/lo split: W[K,N] -> out[N,K] ----------------
__global__ void wconvT_kernel(const float* __restrict__ W,
                              __nv_bfloat16* __restrict__ hi,
                              __nv_bfloat16* __restrict__ lo,
                              int K, int N) {
    __shared__ float t[32][33];
    size_t zoff = (size_t)blockIdx.z * K * N;
    const float* Wl = W + zoff;
    int n0 = blockIdx.x * 32, k0 = blockIdx.y * 32;
    int tx = threadIdx.x, ty = threadIdx.y;
    for (int i = ty; i < 32; i += 8)
        t[i][tx] = Wl[(size_t)(k0 + i) * N + n0 + tx];
    __syncthreads();
    for (int i = ty; i < 32; i += 8) {
        float v = t[tx][i];  // = W[k0+tx][n0+i]
        __nv_bfloat16 h = __float2bfloat16(v);
        size_t o = zoff + (size_t)(n0 + i) * K + k0 + tx;
        hi[o] = h;
        lo[o] = __float2bfloat16(v - __bfloat162float(h));
    }
}

__global__ void wte_conv_kernel(const float* __restrict__ W,
                                __nv_bfloat16* __restrict__ hi,
                                __nv_bfloat16* __restrict__ lo, int n) {
    int i = blockIdx.x * 256 + threadIdx.x;
    if (i < n) {
        float v = W[i];
        __nv_bfloat16 h = __float2bfloat16(v);
        hi[i] = h;
        lo[i] = __float2bfloat16(v - __bfloat162float(h));
    }
}

// ---------------- HMMA GEMM: C[M,N] = (Ahi+Alo)[M,K] @ (Bhi+Blo)[N,K]^T ----------------
// CTA tile 128x128, K-chunk 64 (bf16), double-buffered cp.async, 8 warps (2m x 4n),
// warp tile 64x32, m16n8k16 bf16 mma, fp32 register accumulators across 3 split segs.
// EPI: 0 = +bias -> fp32 | 1 = +bias+res -> fp32 | 2 = +bias,gelu -> bf16 hi/lo | 3 = plain fp32 (N-guarded)
#define GSMEM 65536

template<int EPI>
__global__ __launch_bounds__(256, 2) void mm_gemm(
    const __nv_bfloat16* __restrict__ Ahi, const __nv_bfloat16* __restrict__ Alo,
    const __nv_bfloat16* __restrict__ Bhi, const __nv_bfloat16* __restrict__ Blo,
    const float* __restrict__ bias, const float* __restrict__ res,
    float* __restrict__ outF,
    __nv_bfloat16* __restrict__ outHi, __nv_bfloat16* __restrict__ outLo,
    int M, int N, int K)
{
    extern __shared__ char smem[];
    uint32_t sb = smem_u32(smem);
    const int m0 = blockIdx.x * 128;
    const int n0 = blockIdx.y * 128;
    const int tid  = threadIdx.x;
    const int warp = tid >> 5, lane = tid & 31;
    const int wm = warp >> 2, wn = warp & 3;     // 2 x 4 warp grid

    float acc[4][4][4] = {};                      // [mt][nt][frag]
    const int kc  = K >> 6;
    const int NIT = 3 * kc;

    auto issue = [&](int it) {
        const int buf = it & 1;
        const int seg = it / kc;
        const int kb  = it - seg * kc;
        const __nv_bfloat16* Ap = (seg == 1) ? Alo : Ahi;
        const __nv_bfloat16* Bp = (seg == 2) ? Blo : Bhi;
        const size_t koff = (size_t)kb * 64;
        const uint32_t aB = sb + buf * 32768;
        const uint32_t bB = aB + 16384;
        #pragma unroll
        for (int c = 0; c < 4; c++) {           // A: 128 rows x 128B
            int idx = tid + c * 256;
            int r = idx >> 3, g16 = idx & 7;
            cpasync16(aB + SWZ(r * 128 + g16 * 16),
                      Ap + (size_t)(m0 + r) * K + koff + g16 * 8, 16);
        }
        #pragma unroll
        for (int c = 0; c < 4; c++) {           // B: 128 rows x 128B (guarded)
            int idx = tid + c * 256;
            int r = idx >> 3, g16 = idx & 7;
            int n = n0 + r;
            int ok = (n < N);
            cpasync16(bB + SWZ(r * 128 + g16 * 16),
                      Bp + (size_t)(ok ? n : 0) * K + koff + g16 * 8, ok ? 16 : 0);
        }
        cp_commit();
    };

    issue(0);
    for (int it = 0; it < NIT; ++it) {
        const int buf = it & 1;
        if (it + 1 < NIT) { issue(it + 1); cp_wait1(); }
        else              { cp_wait0(); }
        __syncthreads();

        const uint32_t aB = sb + buf * 32768;
        const uint32_t bB = aB + 16384;
        #pragma unroll
        for (int ks = 0; ks < 4; ks++) {
            uint32_t a[4][4], b[4][2];
            #pragma unroll
            for (int mt = 0; mt < 4; mt++) {
                int mrow = wm * 64 + mt * 16 + (lane & 15);
                ldsm4(a[mt], aB + SWZ(mrow * 128 + ks * 32 + (lane >> 4) * 16));
            }
            #pragma unroll
            for (int p = 0; p < 2; p++) {       // two n-tiles per ldmatrix.x4
                int q = lane >> 3;
                int nrow = wn * 32 + p * 16 + (q >> 1) * 8 + (lane & 7);
                uint32_t t4[4];
                ldsm4(t4, bB + SWZ(nrow * 128 + ks * 32 + (q & 1) * 16));
                b[2 * p][0] = t4[0]; b[2 * p][1] = t4[1];
                b[2 * p + 1][0] = t4[2]; b[2 * p + 1][1] = t4[3];
            }
            #pragma unroll
            for (int mt = 0; mt < 4; mt++)
                #pragma unroll
                for (int nt = 0; nt < 4; nt++)
                    mma16816(acc[mt][nt], a[mt], b[nt]);
        }
        __syncthreads();
    }

    // ---------------- epilogue: direct register -> global ----------------
    const int g = lane >> 2, tig = lane & 3;
    #pragma unroll
    for (int mt = 0; mt < 4; mt++) {
        #pragma unroll
        for (int nt = 0; nt < 4; nt++) {
            int nc = n0 + wn * 32 + nt * 8 + tig * 2;
            #pragma unroll
            for (int h = 0; h < 2; h++) {       // row g / row g+8
                int m = m0 + wm * 64 + mt * 16 + g + h * 8;
                float v0 = acc[mt][nt][2 * h];
                float v1 = acc[mt][nt][2 * h + 1];
                size_t gi = (size_t)m * N + nc;
                if (EPI == 3) {
                    if (nc     < N) outF[gi]     = v0;
                    if (nc + 1 < N) outF[gi + 1] = v1;
                } else {
                    v0 += bias[nc]; v1 += bias[nc + 1];
                    if (EPI == 2) {
                        v0 *= normcdff(v0); v1 *= normcdff(v1);
                        __nv_bfloat16 h0 = __float2bfloat16(v0);
                        __nv_bfloat16 h1 = __float2bfloat16(v1);
                        __nv_bfloat162 hv; hv.x = h0; hv.y = h1;
                        __nv_bfloat162 lv;
                        lv.x = __float2bfloat16(v0 - __bfloat162float(h0));
                        lv.y = __float2bfloat16(v1 - __bfloat162float(h1));
                        *reinterpret_cast<__nv_bfloat162*>(outHi + gi) = hv;
                        *reinterpret_cast<__nv_bfloat162*>(outLo + gi) = lv;
                    } else {
                        if (EPI == 1) {
                            float2 r2 = *reinterpret_cast<const float2*>(res + gi);
                            v0 += r2.x; v1 += r2.y;
                        }
                        float2 o2; o2.x = v0; o2.y = v1;
                        *reinterpret_cast<float2*>(outF + gi) = o2;
                    }
                }
            }
        }
    }
}

// ---------------- attention: 4 queries / block, 128 threads, bf16 hi/lo out ----------------
__global__ __launch_bounds__(128, 4) void attn_kernel(const float* __restrict__ qkv,
                                                      __nv_bfloat16* __restrict__ ohi,
                                                      __nv_bfloat16* __restrict__ olo) {
    const int q0  = blockIdx.x * 4;
    const int n   = blockIdx.y;
    const int b   = blockIdx.z;
    const int tid = threadIdx.x;
    __shared__ float qs[4][64];
    __shared__ float sc[4][Tlen];
    __shared__ float red[128];
    __shared__ float mxs[4], sms[4];
    __shared__ float part[2][4][64];

    const float* base = qkv + (size_t)b * Tlen * (3 * Dm);

    for (int i = tid; i < 256; i += 128) {
        int qq = i >> 6, d = i & 63;
        qs[qq][d] = base[(size_t)(q0 + qq) * (3 * Dm) + n * 64 + d];
    }
    __syncthreads();

    const int kmax = q0 + 3;

    float lm[4] = { -1e30f, -1e30f, -1e30f, -1e30f };
    for (int k = tid; k <= kmax; k += 128) {
        const float* kr = base + (size_t)k * (3 * Dm) + Dm + n * 64;
        float s[4] = {0.f, 0.f, 0.f, 0.f};
        #pragma unroll
        for (int d = 0; d < 64; d += 4) {
            float4 kv = *(const float4*)(kr + d);
            #pragma unroll
            for (int qq = 0; qq < 4; qq++)
                s[qq] += kv.x * qs[qq][d] + kv.y * qs[qq][d + 1]
                       + kv.z * qs[qq][d + 2] + kv.w * qs[qq][d + 3];
        }
        #pragma unroll
        for (int qq = 0; qq < 4; qq++) {
            float sv = (k <= q0 + qq) ? s[qq] * 0.125f : -1e30f;
            sc[qq][k] = sv;
            lm[qq] = fmaxf(lm[qq], sv);
        }
    }
    for (int qq = 0; qq < 4; qq++) {
        red[tid] = lm[qq];
        __syncthreads();
        #pragma unroll
        for (int s = 64; s > 0; s >>= 1) {
            if (tid < s) red[tid] = fmaxf(red[tid], red[tid + s]);
            __syncthreads();
        }
        if (tid == 0) mxs[qq] = red[0];
        __syncthreads();
    }
    float ls[4] = {0.f, 0.f, 0.f, 0.f};
    for (int k = tid; k <= kmax; k += 128) {
        #pragma unroll
        for (int qq = 0; qq < 4; qq++) {
            float e = expf(sc[qq][k] - mxs[qq]);
            sc[qq][k] = e;
            ls[qq] += e;
        }
    }
    for (int qq = 0; qq < 4; qq++) {
        red[tid] = ls[qq];
        __syncthreads();
        #pragma unroll
        for (int s = 64; s > 0; s >>= 1) {
            if (tid < s) red[tid] += red[tid + s];
            __syncthreads();
        }
        if (tid == 0) sms[qq] = red[0];
        __syncthreads();
    }
    {
        int d = tid & 63, h = tid >> 6;
        float a[4] = {0.f, 0.f, 0.f, 0.f};
        for (int k = h; k <= kmax; k += 2) {
            float vv = base[(size_t)k * (3 * Dm) + 2 * Dm + n * 64 + d];
            #pragma unroll
            for (int qq = 0; qq < 4; qq++) a[qq] += sc[qq][k] * vv;
        }
        #pragma unroll
        for (int qq = 0; qq < 4; qq++) part[h][qq][d] = a[qq];
        __syncthreads();
        if (h == 0) {
            #pragma unroll
            for (int qq = 0; qq < 4; qq++) {
                float o = (part[0][qq][d] + part[1][qq][d]) / sms[qq];
                size_t gi = (size_t)(b * Tlen + q0 + qq) * Dm + n * 64 + d;
                __nv_bfloat16 hh = __float2bfloat16(o);
                ohi[gi] = hh;
                olo[gi] = __float2bfloat16(o - __bfloat162float(hh));
            }
        }
    }
}

// ---------------- host driver ----------------
extern "C" void kernel_launch(void* const* d_in, const int* in_sizes, int n_in,
                              void* d_out, int out_size) {
    const int*   tokens      = (const int*)  d_in[0];
    const float* wte         = (const float*)d_in[1];
    const float* wpe         = (const float*)d_in[2];
    const float* ln1_g       = (const float*)d_in[3];
    const float* ln1_b       = (const float*)d_in[4];
    const float* attn_w      = (const float*)d_in[5];
    const float* attn_b      = (const float*)d_in[6];
    const float* attn_proj_w = (const float*)d_in[7];
    const float* attn_proj_b = (const float*)d_in[8];
    const float* ln2_g       = (const float*)d_in[9];
    const float* ln2_b       = (const float*)d_in[10];
    const float* fc_w        = (const float*)d_in[11];
    const float* fc_b        = (const float*)d_in[12];
    const float* mlp_proj_w  = (const float*)d_in[13];
    const float* mlp_proj_b  = (const float*)d_in[14];
    const float* lnf_g       = (const float*)d_in[15];
    const float* lnf_b       = (const float*)d_in[16];
    float* out = (float*)d_out;

    float *xp, *qkvp;
    __nv_bfloat16 *hhi, *hlo, *ahi, *alo, *fchi, *fclo;
    __nv_bfloat16 *qh, *ql, *aph, *apl, *fch, *fcl, *mph, *mpl, *teh, *tel;
    cudaGetSymbolAddress((void**)&xp,   g_x);
    cudaGetSymbolAddress((void**)&qkvp, g_qkv);
    cudaGetSymbolAddress((void**)&hhi,  g_hhi);  cudaGetSymbolAddress((void**)&hlo,  g_hlo);
    cudaGetSymbolAddress((void**)&ahi,  g_ahi);  cudaGetSymbolAddress((void**)&alo,  g_alo);
    cudaGetSymbolAddress((void**)&fchi, g_fchi); cudaGetSymbolAddress((void**)&fclo, g_fclo);
    cudaGetSymbolAddress((void**)&qh,  w_qkv_hi); cudaGetSymbolAddress((void**)&ql,  w_qkv_lo);
    cudaGetSymbolAddress((void**)&aph, w_ap_hi);  cudaGetSymbolAddress((void**)&apl, w_ap_lo);
    cudaGetSymbolAddress((void**)&fch, w_fc_hi);  cudaGetSymbolAddress((void**)&fcl, w_fc_lo);
    cudaGetSymbolAddress((void**)&mph, w_mp_hi);  cudaGetSymbolAddress((void**)&mpl, w_mp_lo);
    cudaGetSymbolAddress((void**)&teh, w_te_hi);  cudaGetSymbolAddress((void**)&tel, w_te_lo);

    cudaFuncSetAttribute(mm_gemm<0>, cudaFuncAttributeMaxDynamicSharedMemorySize, GSMEM);
    cudaFuncSetAttribute(mm_gemm<1>, cudaFuncAttributeMaxDynamicSharedMemorySize, GSMEM);
    cudaFuncSetAttribute(mm_gemm<2>, cudaFuncAttributeMaxDynamicSharedMemorySize, GSMEM);
    cudaFuncSetAttribute(mm_gemm<3>, cudaFuncAttributeMaxDynamicSharedMemorySize, GSMEM);

    // weight conversion (transpose + hi/lo split) every call (deterministic)
    dim3 wb(32, 8);
    wconvT_kernel<<<dim3(3*Dm/32, Dm/32, Lc), wb>>>(attn_w,      qh,  ql,  Dm, 3*Dm);
    wconvT_kernel<<<dim3(Dm/32,   Dm/32, Lc), wb>>>(attn_proj_w, aph, apl, Dm, Dm);
    wconvT_kernel<<<dim3(Fm/32,   Dm/32, Lc), wb>>>(fc_w,        fch, fcl, Dm, Fm);
    wconvT_kernel<<<dim3(Dm/32,   Fm/32, Lc), wb>>>(mlp_proj_w,  mph, mpl, Fm, Dm);
    wte_conv_kernel<<<(Vv*Dm + 255)/256, 256>>>(wte, teh, tel, Vv*Dm);

    embed_kernel<<<Rows, 256>>>(tokens, wte, wpe, xp);

    const dim3 gQKV(Rows/128, (3*Dm)/128);
    const dim3 gP  (Rows/128, Dm/128);
    const dim3 gF  (Rows/128, Fm/128);
    const dim3 gV  (Rows/128, (Vv + 127)/128);
    const dim3 gAtt(Tlen/4, Nh, Bsz);

    for (int l = 0; l < Lc; l++) {
        ln_kernel<<<Rows, 256>>>(xp, ln1_g + l*Dm, ln1_b + l*Dm, hhi, hlo);
        mm_gemm<0><<<gQKV, 256, GSMEM>>>(hhi, hlo,
            qh + (size_t)l*3*Dm*Dm, ql + (size_t)l*3*Dm*Dm,
            attn_b + (size_t)l*3*Dm, nullptr, qkvp, nullptr, nullptr,
            Rows, 3*Dm, Dm);
        attn_kernel<<<gAtt, 128>>>(qkvp, ahi, alo);
        mm_gemm<1><<<gP, 256, GSMEM>>>(ahi, alo,
            aph + (size_t)l*Dm*Dm, apl + (size_t)l*Dm*Dm,
            attn_proj_b + (size_t)l*Dm, xp, xp, nullptr, nullptr,
            Rows, Dm, Dm);
        ln_kernel<<<Rows, 256>>>(xp, ln2_g + l*Dm, ln2_b + l*Dm, hhi, hlo);
        mm_gemm<2><<<gF, 256, GSMEM>>>(hhi, hlo,
            fch + (size_t)l*Fm*Dm, fcl + (size_t)l*Fm*Dm,
            fc_b + (size_t)l*Fm, nullptr, nullptr, fchi, fclo,
            Rows, Fm, Dm);
        mm_gemm<1><<<gP, 256, GSMEM>>>(fchi, fclo,
            mph + (size_t)l*Dm*Fm, mpl + (size_t)l*Dm*Fm,
            mlp_proj_b + (size_t)l*Dm, xp, xp, nullptr, nullptr,
            Rows, Dm, Fm);
    }

    ln_kernel<<<Rows, 256>>>(xp, lnf_g, lnf_b, hhi, hlo);
    mm_gemm<3><<<gV, 256, GSMEM>>>(hhi, hlo, teh, tel,
        nullptr, nullptr, out, nullptr, nullptr,
        Rows, Vv, Dm);
}

// round 4
// speedup vs baseline: 2.7581x; 1.4409x over previous
#include <cuda_runtime.h>
#include <cuda_bf16.h>
#include <math.h>
#include <stdint.h>

#define Bsz 4
#define Tlen 1024
#define Dm 768
#define Nh 12
#define Fm 3072
#define Lc 12
#define Vv 50257
#define Rows (Bsz*Tlen)   /* 4096 */
#define QT 16             /* attention queries per block */

// ---------------- scratch (static device globals; no allocation) ----------------
__device__ float g_x[Rows*Dm];                             // residual stream (fp32)
__device__ __nv_bfloat16 g_hhi[Rows*Dm], g_hlo[Rows*Dm];   // LN output hi/lo
__device__ float g_qkv[Rows*3*Dm];
__device__ __nv_bfloat16 g_ahi[Rows*Dm], g_alo[Rows*Dm];   // attn out hi/lo
__device__ __nv_bfloat16 g_fchi[Rows*Fm], g_fclo[Rows*Fm]; // gelu(fc) hi/lo
// transposed + split weights [N,K]
__device__ __nv_bfloat16 w_qkv_hi[Lc*3*Dm*Dm], w_qkv_lo[Lc*3*Dm*Dm];
__device__ __nv_bfloat16 w_ap_hi [Lc*Dm*Dm],   w_ap_lo [Lc*Dm*Dm];
__device__ __nv_bfloat16 w_fc_hi [Lc*Fm*Dm],   w_fc_lo [Lc*Fm*Dm];
__device__ __nv_bfloat16 w_mp_hi [Lc*Dm*Fm],   w_mp_lo [Lc*Dm*Fm];
__device__ __nv_bfloat16 w_te_hi [Vv*Dm],      w_te_lo [Vv*Dm];

// ---------------- helpers ----------------
__device__ __forceinline__ uint32_t smem_u32(const void* p) {
    uint32_t a;
    asm("{ .reg .u64 t; cvta.to.shared.u64 t, %1; cvt.u32.u64 %0, t; }" : "=r"(a) : "l"(p));
    return a;
}
#define SWZ(o) ((o) ^ ((((uint32_t)(o)) >> 3) & 0x70))

__device__ __forceinline__ void cpasync16(uint32_t s, const void* g, uint32_t sz) {
    asm volatile("cp.async.cg.shared.global [%0], [%1], 16, %2;\n"
                 :: "r"(s), "l"(g), "r"(sz) : "memory");
}
__device__ __forceinline__ void cpasync16f(uint32_t s, const void* g) {
    asm volatile("cp.async.cg.shared.global [%0], [%1], 16;\n"
                 :: "r"(s), "l"(g) : "memory");
}
__device__ __forceinline__ void cp_commit() {
    asm volatile("cp.async.commit_group;\n" ::: "memory");
}
__device__ __forceinline__ void cp_wait1() {
    asm volatile("cp.async.wait_group 1;\n" ::: "memory");
}
__device__ __forceinline__ void ldsm4(uint32_t r[4], uint32_t addr) {
    asm volatile("ldmatrix.sync.aligned.m8n8.x4.shared.b16 {%0,%1,%2,%3}, [%4];"
                 : "=r"(r[0]), "=r"(r[1]), "=r"(r[2]), "=r"(r[3]) : "r"(addr));
}
__device__ __forceinline__ void mma16816(float c[4], const uint32_t a[4], const uint32_t b[2]) {
    asm volatile("mma.sync.aligned.m16n8k16.row.col.f32.bf16.bf16.f32 "
                 "{%0,%1,%2,%3}, {%4,%5,%6,%7}, {%8,%9}, {%0,%1,%2,%3};"
                 : "+f"(c[0]), "+f"(c[1]), "+f"(c[2]), "+f"(c[3])
                 : "r"(a[0]), "r"(a[1]), "r"(a[2]), "r"(a[3]), "r"(b[0]), "r"(b[1]));
}

// ---------------- embedding ----------------
__global__ void embed_kernel(const int* __restrict__ tokens,
                             const float* __restrict__ wte,
                             const float* __restrict__ wpe,
                             float* __restrict__ x) {
    int row = blockIdx.x;
    int t   = row % Tlen;
    int tok = tokens[row];
    const float* we = wte + (size_t)tok * Dm;
    const float* pe = wpe + (size_t)t   * Dm;
    float* xr = x + (size_t)row * Dm;
    for (int i = threadIdx.x; i < Dm; i += blockDim.x)
        xr[i] = we[i] + pe[i];
}

// ---------------- layernorm -> bf16 hi/lo ----------------
__global__ void ln_kernel(const float* __restrict__ x,
                          const float* __restrict__ g,
                          const float* __restrict__ b,
                          __nv_bfloat16* __restrict__ ohi,
                          __nv_bfloat16* __restrict__ olo) {
    int row = blockIdx.x;
    int tid = threadIdx.x;
    const float* xr = x + (size_t)row * Dm;
    float v0 = xr[tid], v1 = xr[tid + 256], v2 = xr[tid + 512];
    __shared__ float red[256];
    red[tid] = v0 + v1 + v2;
    __syncthreads();
    #pragma unroll
    for (int s = 128; s > 0; s >>= 1) { if (tid < s) red[tid] += red[tid + s]; __syncthreads(); }
    float mean = red[0] * (1.0f / Dm);
    __syncthreads();
    float d0 = v0 - mean, d1 = v1 - mean, d2 = v2 - mean;
    red[tid] = d0 * d0 + d1 * d1 + d2 * d2;
    __syncthreads();
    #pragma unroll
    for (int s = 128; s > 0; s >>= 1) { if (tid < s) red[tid] += red[tid + s]; __syncthreads(); }
    float rstd = rsqrtf(red[0] * (1.0f / Dm) + 1e-5f);
    size_t base = (size_t)row * Dm;
    #pragma unroll
    for (int j = 0; j < 3; j++) {
        int i = tid + j * 256;
        float dd = (j == 0) ? d0 : (j == 1) ? d1 : d2;
        float v = dd * rstd * g[i] + b[i];
        __nv_bfloat16 h = __float2bfloat16(v);
        ohi[base + i] = h;
        olo[base + i] = __float2bfloat16(v - __bfloat162float(h));
    }
}

// ---------------- weight transpose + hi/lo split: W[K,N] -> out[N,K] ----------------
__global__ void wconvT_kernel(const float* __restrict__ W,
                              __nv_bfloat16* __restrict__ hi,
                              __nv_bfloat16* __restrict__ lo,
                              int K, int N) {
    __shared__ float t[32][33];
    size_t zoff = (size_t)blockIdx.z * K * N;
    const float* Wl = W + zoff;
    int n0 = blockIdx.x * 32, k0 = blockIdx.y * 32;
    int tx = threadIdx.x, ty = threadIdx.y;
    for (int i = ty; i < 32; i += 8)
        t[i][tx] = Wl[(size_t)(k0 + i) * N + n0 + tx];
    __syncthreads();
    for (int i = ty; i < 32; i += 8) {
        float v = t[tx][i];  // = W[k0+tx][n0+i]
        __nv_bfloat16 h = __float2bfloat16(v);
        size_t o = zoff + (size_t)(n0 + i) * K + k0 + tx;
        hi[o] = h;
        lo[o] = __float2bfloat16(v - __bfloat162float(h));
    }
}

__global__ void wte_conv_kernel(const float* __restrict__ W,
                                __nv_bfloat16* __restrict__ hi,
                                __nv_bfloat16* __restrict__ lo, int n) {
    int i = blockIdx.x * 256 + threadIdx.x;
    if (i < n) {
        float v = W[i];
        __nv_bfloat16 h = __float2bfloat16(v);
        hi[i] = h;
        lo[i] = __float2bfloat16(v - __bfloat162float(h));
    }
}

// ---------------- HMMA GEMM: C[M,N] = (Ahi+Alo)[M,K] @ (Bhi+Blo)[N,K]^T ----------------
// CTA tile 128x128, K-chunk 64 (bf16), 3-stage cp.async pipeline (one sync/iter),
// 8 warps (2m x 4n), warp tile 64x32, m16n8k16 bf16 mma, fp32 register accumulators.
// EPI: 0 = +bias -> fp32 | 1 = +bias+res -> fp32 | 2 = +bias,gelu -> bf16 hi/lo | 3 = plain fp32
#define GSMEM 98304

template<int EPI, bool GUARD>
__global__ __launch_bounds__(256, 2) void mm_gemm(
    const __nv_bfloat16* __restrict__ Ahi, const __nv_bfloat16* __restrict__ Alo,
    const __nv_bfloat16* __restrict__ Bhi, const __nv_bfloat16* __restrict__ Blo,
    const float* __restrict__ bias, const float* __restrict__ res,
    float* __restrict__ outF,
    __nv_bfloat16* __restrict__ outHi, __nv_bfloat16* __restrict__ outLo,
    int M, int N, int K)
{
    extern __shared__ char smem[];
    uint32_t sb = smem_u32(smem);
    const int m0 = blockIdx.x * 128;
    const int n0 = blockIdx.y * 128;
    const int tid  = threadIdx.x;
    const int warp = tid >> 5, lane = tid & 31;
    const int wm = warp >> 2, wn = warp & 3;     // 2 x 4 warp grid

    float acc[4][4][4] = {};                      // [mt][nt][frag]
    const int kc  = K >> 6;
    const int NIT = 3 * kc;

    auto issue = [&](int it) {
        const int st  = it % 3;
        const int seg = it / kc;
        const int kb  = it - seg * kc;
        const __nv_bfloat16* Ap = (seg == 1) ? Alo : Ahi;
        const __nv_bfloat16* Bp = (seg == 2) ? Blo : Bhi;
        const size_t koff = (size_t)kb * 64;
        const uint32_t aB = sb + st * 32768;
        const uint32_t bB = aB + 16384;
        #pragma unroll
        for (int c = 0; c < 4; c++) {           // A: 128 rows x 128B
            int idx = tid + c * 256;
            int r = idx >> 3, g16 = idx & 7;
            cpasync16f(aB + SWZ(r * 128 + g16 * 16),
                       Ap + (size_t)(m0 + r) * K + koff + g16 * 8);
        }
        #pragma unroll
        for (int c = 0; c < 4; c++) {           // B: 128 rows x 128B
            int idx = tid + c * 256;
            int r = idx >> 3, g16 = idx & 7;
            if (GUARD) {
                int n = n0 + r;
                int ok = (n < N);
                cpasync16(bB + SWZ(r * 128 + g16 * 16),
                          Bp + (size_t)(ok ? n : 0) * K + koff + g16 * 8, ok ? 16 : 0);
            } else {
                cpasync16f(bB + SWZ(r * 128 + g16 * 16),
                           Bp + (size_t)(n0 + r) * K + koff + g16 * 8);
            }
        }
        cp_commit();
    };

    issue(0);
    issue(1);
    for (int it = 0; it < NIT; ++it) {
        cp_wait1();            // group(it) complete (only it+1 may remain)
        __syncthreads();       // all warps see stage data; all done with it-1 reads
        if (it + 2 < NIT) issue(it + 2);   // overwrites stage (it-1)%3 — safe after sync

        const uint32_t aB = sb + (it % 3) * 32768;
        const uint32_t bB = aB + 16384;
        #pragma unroll
        for (int ks = 0; ks < 4; ks++) {
            uint32_t a[4][4], b[4][2];
            #pragma unroll
            for (int mt = 0; mt < 4; mt++) {
                int mrow = wm * 64 + mt * 16 + (lane & 15);
                ldsm4(a[mt], aB + SWZ(mrow * 128 + ks * 32 + (lane >> 4) * 16));
            }
            #pragma unroll
            for (int p = 0; p < 2; p++) {       // two n-tiles per ldmatrix.x4
                int q = lane >> 3;
                int nrow = wn * 32 + p * 16 + (q >> 1) * 8 + (lane & 7);
                uint32_t t4[4];
                ldsm4(t4, bB + SWZ(nrow * 128 + ks * 32 + (q & 1) * 16));
                b[2 * p][0] = t4[0]; b[2 * p][1] = t4[1];
                b[2 * p + 1][0] = t4[2]; b[2 * p + 1][1] = t4[3];
            }
            #pragma unroll
            for (int mt = 0; mt < 4; mt++)
                #pragma unroll
                for (int nt = 0; nt < 4; nt++)
                    mma16816(acc[mt][nt], a[mt], b[nt]);
        }
    }

    // ---------------- epilogue: direct register -> global ----------------
    const int g = lane >> 2, tig = lane & 3;
    #pragma unroll
    for (int mt = 0; mt < 4; mt++) {
        #pragma unroll
        for (int nt = 0; nt < 4; nt++) {
            int nc = n0 + wn * 32 + nt * 8 + tig * 2;
            #pragma unroll
            for (int h = 0; h < 2; h++) {       // row g / row g+8
                int m = m0 + wm * 64 + mt * 16 + g + h * 8;
                float v0 = acc[mt][nt][2 * h];
                float v1 = acc[mt][nt][2 * h + 1];
                size_t gi = (size_t)m * N + nc;
                if (EPI == 3) {
                    if (!GUARD || nc < N)     outF[gi]     = v0;
                    if (!GUARD || nc + 1 < N) outF[gi + 1] = v1;
                } else {
                    v0 += bias[nc]; v1 += bias[nc + 1];
                    if (EPI == 2) {
                        v0 *= normcdff(v0); v1 *= normcdff(v1);
                        __nv_bfloat16 h0 = __float2bfloat16(v0);
                        __nv_bfloat16 h1 = __float2bfloat16(v1);
                        __nv_bfloat162 hv; hv.x = h0; hv.y = h1;
                        __nv_bfloat162 lv;
                        lv.x = __float2bfloat16(v0 - __bfloat162float(h0));
                        lv.y = __float2bfloat16(v1 - __bfloat162float(h1));
                        *reinterpret_cast<__nv_bfloat162*>(outHi + gi) = hv;
                        *reinterpret_cast<__nv_bfloat162*>(outLo + gi) = lv;
                    } else {
                        if (EPI == 1) {
                            float2 r2 = *reinterpret_cast<const float2*>(res + gi);
                            v0 += r2.x; v1 += r2.y;
                        }
                        float2 o2; o2.x = v0; o2.y = v1;
                        *reinterpret_cast<float2*>(outF + gi) = o2;
                    }
                }
            }
        }
    }
}

// ---------------- attention: 16 queries / block, 256 threads, bf16 hi/lo out ----------------
// dynamic smem layout: sc[QT][1040] | qs[QT][64] | part[4][QT][64] | red[QT*8]
#define ASC_STRIDE 1040
#define ASMEM ((QT*ASC_STRIDE + QT*64 + 4*QT*64 + QT*8) * 4)

__global__ __launch_bounds__(256, 2) void attn_kernel(const float* __restrict__ qkv,
                                                      __nv_bfloat16* __restrict__ ohi,
                                                      __nv_bfloat16* __restrict__ olo) {
    extern __shared__ float As[];
    float* sc   = As;                              // [QT][ASC_STRIDE]
    float* qs   = As + QT * ASC_STRIDE;            // [QT][64]
    float* part = qs + QT * 64;                    // [4][QT][64]
    float* red  = part + 4 * QT * 64;              // [QT][8]
    __shared__ float mxs[QT], sms[QT];

    const int q0  = blockIdx.x * QT;
    const int n   = blockIdx.y;
    const int b   = blockIdx.z;
    const int tid = threadIdx.x;
    const int lane = tid & 31, warp = tid >> 5;

    const float* base = qkv + (size_t)b * Tlen * (3 * Dm);

    for (int i = tid; i < QT * 64; i += 256) {
        int qq = i >> 6, d = i & 63;
        qs[qq * 64 + d] = base[(size_t)(q0 + qq) * (3 * Dm) + n * 64 + d];
    }
    __syncthreads();

    const int kmax = q0 + QT - 1;

    // ---- phase 1: scores + local max ----
    float lm[QT];
    #pragma unroll
    for (int qq = 0; qq < QT; qq++) lm[qq] = -1e30f;
    for (int k = tid; k <= kmax; k += 256) {
        const float* kr = base + (size_t)k * (3 * Dm) + Dm + n * 64;
        float s[QT];
        #pragma unroll
        for (int qq = 0; qq < QT; qq++) s[qq] = 0.f;
        #pragma unroll
        for (int d = 0; d < 64; d += 4) {
            float4 kv = *(const float4*)(kr + d);
            #pragma unroll
            for (int qq = 0; qq < QT; qq++) {
                float4 qv = *(const float4*)(qs + qq * 64 + d);
                s[qq] += kv.x * qv.x + kv.y * qv.y + kv.z * qv.z + kv.w * qv.w;
            }
        }
        #pragma unroll
        for (int qq = 0; qq < QT; qq++) {
            float sv = (k <= q0 + qq) ? s[qq] * 0.125f : -1e30f;
            sc[qq * ASC_STRIDE + k] = sv;
            lm[qq] = fmaxf(lm[qq], sv);
        }
    }
    #pragma unroll
    for (int qq = 0; qq < QT; qq++) {
        #pragma unroll
        for (int o = 16; o > 0; o >>= 1)
            lm[qq] = fmaxf(lm[qq], __shfl_xor_sync(0xffffffffu, lm[qq], o));
    }
    if (lane == 0) {
        #pragma unroll
        for (int qq = 0; qq < QT; qq++) red[qq * 8 + warp] = lm[qq];
    }
    __syncthreads();
    if (tid < QT) {
        float m = -1e30f;
        #pragma unroll
        for (int w = 0; w < 8; w++) m = fmaxf(m, red[tid * 8 + w]);
        mxs[tid] = m;
    }
    __syncthreads();

    // ---- phase 2: exp + local sum ----
    float mx[QT];
    #pragma unroll
    for (int qq = 0; qq < QT; qq++) mx[qq] = mxs[qq];
    float ls[QT];
    #pragma unroll
    for (int qq = 0; qq < QT; qq++) ls[qq] = 0.f;
    for (int k = tid; k <= kmax; k += 256) {
        #pragma unroll
        for (int qq = 0; qq < QT; qq++) {
            float e = __expf(sc[qq * ASC_STRIDE + k] - mx[qq]);
            sc[qq * ASC_STRIDE + k] = e;
            ls[qq] += e;
        }
    }
    #pragma unroll
    for (int qq = 0; qq < QT; qq++) {
        #pragma unroll
        for (int o = 16; o > 0; o >>= 1)
            ls[qq] += __shfl_xor_sync(0xffffffffu, ls[qq], o);
    }
    if (lane == 0) {
        #pragma unroll
        for (int qq = 0; qq < QT; qq++) red[qq * 8 + warp] = ls[qq];
    }
    __syncthreads();
    if (tid < QT) {
        float s = 0.f;
        #pragma unroll
        for (int w = 0; w < 8; w++) s += red[tid * 8 + w];
        sms[tid] = s;
    }
    __syncthreads();

    // ---- phase 3: o = P @ V ----
    {
        const int d = tid & 63, h = tid >> 6;     // 4 k-slices
        const int kcount = q0 + QT;               // multiple of 16
        const int chunk  = kcount >> 2;           // multiple of 4
        const int klo = h * chunk, khi = klo + chunk;
        float a[QT];
        #pragma unroll
        for (int qq = 0; qq < QT; qq++) a[qq] = 0.f;
        const float* vb = base + 2 * Dm + n * 64 + d;
        for (int k = klo; k < khi; k += 4) {
            float vv0 = vb[(size_t)(k + 0) * (3 * Dm)];
            float vv1 = vb[(size_t)(k + 1) * (3 * Dm)];
            float vv2 = vb[(size_t)(k + 2) * (3 * Dm)];
            float vv3 = vb[(size_t)(k + 3) * (3 * Dm)];
            #pragma unroll
            for (int qq = 0; qq < QT; qq++) {
                float4 p = *(const float4*)(sc + qq * ASC_STRIDE + k);
                a[qq] += p.x * vv0 + p.y * vv1 + p.z * vv2 + p.w * vv3;
            }
        }
        #pragma unroll
        for (int qq = 0; qq < QT; qq++) part[(h * QT + qq) * 64 + d] = a[qq];
        __syncthreads();
        if (h == 0) {
            #pragma unroll
            for (int qq = 0; qq < QT; qq++) {
                float o = (part[(0 * QT + qq) * 64 + d] + part[(1 * QT + qq) * 64 + d]
                         + part[(2 * QT + qq) * 64 + d] + part[(3 * QT + qq) * 64 + d]) / sms[qq];
                size_t gi = (size_t)(b * Tlen + q0 + qq) * Dm + n * 64 + d;
                __nv_bfloat16 hh = __float2bfloat16(o);
                ohi[gi] = hh;
                olo[gi] = __float2bfloat16(o - __bfloat162float(hh));
            }
        }
    }
}

// ---------------- host driver ----------------
extern "C" void kernel_launch(void* const* d_in, const int* in_sizes, int n_in,
                              void* d_out, int out_size) {
    const int*   tokens      = (const int*)  d_in[0];
    const float* wte         = (const float*)d_in[1];
    const float* wpe         = (const float*)d_in[2];
    const float* ln1_g       = (const float*)d_in[3];
    const float* ln1_b       = (const float*)d_in[4];
    const float* attn_w      = (const float*)d_in[5];
    const float* attn_b      = (const float*)d_in[6];
    const float* attn_proj_w = (const float*)d_in[7];
    const float* attn_proj_b = (const float*)d_in[8];
    const float* ln2_g       = (const float*)d_in[9];
    const float* ln2_b       = (const float*)d_in[10];
    const float* fc_w        = (const float*)d_in[11];
    const float* fc_b        = (const float*)d_in[12];
    const float* mlp_proj_w  = (const float*)d_in[13];
    const float* mlp_proj_b  = (const float*)d_in[14];
    const float* lnf_g       = (const float*)d_in[15];
    const float* lnf_b       = (const float*)d_in[16];
    float* out = (float*)d_out;

    float *xp, *qkvp;
    __nv_bfloat16 *hhi, *hlo, *ahi, *alo, *fchi, *fclo;
    __nv_bfloat16 *qh, *ql, *aph, *apl, *fch, *fcl, *mph, *mpl, *teh, *tel;
    cudaGetSymbolAddress((void**)&xp,   g_x);
    cudaGetSymbolAddress((void**)&qkvp, g_qkv);
    cudaGetSymbolAddress((void**)&hhi,  g_hhi);  cudaGetSymbolAddress((void**)&hlo,  g_hlo);
    cudaGetSymbolAddress((void**)&ahi,  g_ahi);  cudaGetSymbolAddress((void**)&alo,  g_alo);
    cudaGetSymbolAddress((void**)&fchi, g_fchi); cudaGetSymbolAddress((void**)&fclo, g_fclo);
    cudaGetSymbolAddress((void**)&qh,  w_qkv_hi); cudaGetSymbolAddress((void**)&ql,  w_qkv_lo);
    cudaGetSymbolAddress((void**)&aph, w_ap_hi);  cudaGetSymbolAddress((void**)&apl, w_ap_lo);
    cudaGetSymbolAddress((void**)&fch, w_fc_hi);  cudaGetSymbolAddress((void**)&fcl, w_fc_lo);
    cudaGetSymbolAddress((void**)&mph, w_mp_hi);  cudaGetSymbolAddress((void**)&mpl, w_mp_lo);
    cudaGetSymbolAddress((void**)&teh, w_te_hi);  cudaGetSymbolAddress((void**)&tel, w_te_lo);

    cudaFuncSetAttribute((const void*)mm_gemm<0,false>, cudaFuncAttributeMaxDynamicSharedMemorySize, GSMEM);
    cudaFuncSetAttribute((const void*)mm_gemm<1,false>, cudaFuncAttributeMaxDynamicSharedMemorySize, GSMEM);
    cudaFuncSetAttribute((const void*)mm_gemm<2,false>, cudaFuncAttributeMaxDynamicSharedMemorySize, GSMEM);
    cudaFuncSetAttribute((const void*)mm_gemm<3,true >, cudaFuncAttributeMaxDynamicSharedMemorySize, GSMEM);
    cudaFuncSetAttribute((const void*)attn_kernel, cudaFuncAttributeMaxDynamicSharedMemorySize, ASMEM);

    // weight conversion (transpose + hi/lo split) every call (deterministic)
    dim3 wb(32, 8);
    wconvT_kernel<<<dim3(3*Dm/32, Dm/32, Lc), wb>>>(attn_w,      qh,  ql,  Dm, 3*Dm);
    wconvT_kernel<<<dim3(Dm/32,   Dm/32, Lc), wb>>>(attn_proj_w, aph, apl, Dm, Dm);
    wconvT_kernel<<<dim3(Fm/32,   Dm/32, Lc), wb>>>(fc_w,        fch, fcl, Dm, Fm);
    wconvT_kernel<<<dim3(Dm/32,   Fm/32, Lc), wb>>>(mlp_proj_w,  mph, mpl, Fm, Dm);
    wte_conv_kernel<<<(Vv*Dm + 255)/256, 256>>>(wte, teh, tel, Vv*Dm);

    embed_kernel<<<Rows, 256>>>(tokens, wte, wpe, xp);

    const dim3 gQKV(Rows/128, (3*Dm)/128);
    const dim3 gP  (Rows/128, Dm/128);
    const dim3 gF  (Rows/128, Fm/128);
    const dim3 gV  (Rows/128, (Vv + 127)/128);
    const dim3 gAtt(Tlen/QT, Nh, Bsz);

    for (int l = 0; l < Lc; l++) {
        ln_kernel<<<Rows, 256>>>(xp, ln1_g + l*Dm, ln1_b + l*Dm, hhi, hlo);
        mm_gemm<0,false><<<gQKV, 256, GSMEM>>>(hhi, hlo,
            qh + (size_t)l*3*Dm*Dm, ql + (size_t)l*3*Dm*Dm,
            attn_b + (size_t)l*3*Dm, nullptr, qkvp, nullptr, nullptr,
            Rows, 3*Dm, Dm);
        attn_kernel<<<gAtt, 256, ASMEM>>>(qkvp, ahi, alo);
        mm_gemm<1,false><<<gP, 256, GSMEM>>>(ahi, alo,
            aph + (size_t)l*Dm*Dm, apl + (size_t)l*Dm*Dm,
            attn_proj_b + (size_t)l*Dm, xp, xp, nullptr, nullptr,
            Rows, Dm, Dm);
        ln_kernel<<<Rows, 256>>>(xp, ln2_g + l*Dm, ln2_b + l*Dm, hhi, hlo);
        mm_gemm<2,false><<<gF, 256, GSMEM>>>(hhi, hlo,
            fch + (size_t)l*Fm*Dm, fcl + (size_t)l*Fm*Dm,
            fc_b + (size_t)l*Fm, nullptr, nullptr, fchi, fclo,
            Rows, Fm, Dm);
        mm_gemm<1,false><<<gP, 256, GSMEM>>>(fchi, fclo,
            mph + (size_t)l*Dm*Fm, mpl + (size_t)l*Dm*Fm,
            mlp_proj_b + (size_t)l*Dm, xp, xp, nullptr, nullptr,
            Rows, Dm, Fm);
    }

    ln_kernel<<<Rows, 256>>>(xp, lnf_g, lnf_b, hhi, hlo);
    mm_gemm<3,true><<<gV, 256, GSMEM>>>(hhi, hlo, teh, tel,
        nullptr, nullptr, out, nullptr, nullptr,
        Rows, Vv, Dm);
}

// round 5
// speedup vs baseline: 2.8806x; 1.0444x over previous
#include <cuda_runtime.h>
#include <cuda_bf16.h>
#include <math.h>
#include <stdint.h>

#define Bsz 4
#define Tlen 1024
#define Dm 768
#define Nh 12
#define Fm 3072
#define Lc 12
#define Vv 50257
#define Rows (Bsz*Tlen)   /* 4096 */
#define QT 16             /* attention queries per block */

// ---------------- scratch (static device globals; no allocation) ----------------
__device__ float g_x[Rows*Dm];                             // residual stream (fp32)
__device__ __nv_bfloat16 g_hhi[Rows*Dm], g_hlo[Rows*Dm];   // LN output hi/lo
__device__ float g_qkv[Rows*3*Dm];
__device__ __nv_bfloat16 g_ahi[Rows*Dm], g_alo[Rows*Dm];   // attn out hi/lo
__device__ __nv_bfloat16 g_fchi[Rows*Fm], g_fclo[Rows*Fm]; // gelu(fc) hi/lo
// transposed + split weights [N,K]
__device__ __nv_bfloat16 w_qkv_hi[Lc*3*Dm*Dm], w_qkv_lo[Lc*3*Dm*Dm];
__device__ __nv_bfloat16 w_ap_hi [Lc*Dm*Dm],   w_ap_lo [Lc*Dm*Dm];
__device__ __nv_bfloat16 w_fc_hi [Lc*Fm*Dm],   w_fc_lo [Lc*Fm*Dm];
__device__ __nv_bfloat16 w_mp_hi [Lc*Dm*Fm],   w_mp_lo [Lc*Dm*Fm];
__device__ __nv_bfloat16 w_te_hi [Vv*Dm],      w_te_lo [Vv*Dm];

// ---------------- helpers ----------------
__device__ __forceinline__ uint32_t smem_u32(const void* p) {
    uint32_t a;
    asm("{ .reg .u64 t; cvta.to.shared.u64 t, %1; cvt.u32.u64 %0, t; }" : "=r"(a) : "l"(p));
    return a;
}
#define SWZ(o) ((o) ^ ((((uint32_t)(o)) >> 3) & 0x70))

__device__ __forceinline__ void cpasync16(uint32_t s, const void* g, uint32_t sz) {
    asm volatile("cp.async.cg.shared.global [%0], [%1], 16, %2;\n"
                 :: "r"(s), "l"(g), "r"(sz) : "memory");
}
__device__ __forceinline__ void cpasync16f(uint32_t s, const void* g) {
    asm volatile("cp.async.cg.shared.global [%0], [%1], 16;\n"
                 :: "r"(s), "l"(g) : "memory");
}
__device__ __forceinline__ void cp_commit() {
    asm volatile("cp.async.commit_group;\n" ::: "memory");
}
__device__ __forceinline__ void cp_wait1() {
    asm volatile("cp.async.wait_group 1;\n" ::: "memory");
}
__device__ __forceinline__ void ldsm4(uint32_t r[4], uint32_t addr) {
    asm volatile("ldmatrix.sync.aligned.m8n8.x4.shared.b16 {%0,%1,%2,%3}, [%4];"
                 : "=r"(r[0]), "=r"(r[1]), "=r"(r[2]), "=r"(r[3]) : "r"(addr));
}
__device__ __forceinline__ void mma16816(float c[4], const uint32_t a[4], const uint32_t b[2]) {
    asm volatile("mma.sync.aligned.m16n8k16.row.col.f32.bf16.bf16.f32 "
                 "{%0,%1,%2,%3}, {%4,%5,%6,%7}, {%8,%9}, {%0,%1,%2,%3};"
                 : "+f"(c[0]), "+f"(c[1]), "+f"(c[2]), "+f"(c[3])
                 : "r"(a[0]), "r"(a[1]), "r"(a[2]), "r"(a[3]), "r"(b[0]), "r"(b[1]));
}

// ---------------- embedding ----------------
__global__ void embed_kernel(const int* __restrict__ tokens,
                             const float* __restrict__ wte,
                             const float* __restrict__ wpe,
                             float* __restrict__ x) {
    int row = blockIdx.x;
    int t   = row % Tlen;
    int tok = tokens[row];
    const float* we = wte + (size_t)tok * Dm;
    const float* pe = wpe + (size_t)t   * Dm;
    float* xr = x + (size_t)row * Dm;
    for (int i = threadIdx.x; i < Dm; i += blockDim.x)
        xr[i] = we[i] + pe[i];
}

// ---------------- layernorm -> bf16 hi/lo ----------------
__global__ void ln_kernel(const float* __restrict__ x,
                          const float* __restrict__ g,
                          const float* __restrict__ b,
                          __nv_bfloat16* __restrict__ ohi,
                          __nv_bfloat16* __restrict__ olo) {
    int row = blockIdx.x;
    int tid = threadIdx.x;
    const float* xr = x + (size_t)row * Dm;
    float v0 = xr[tid], v1 = xr[tid + 256], v2 = xr[tid + 512];
    __shared__ float red[256];
    red[tid] = v0 + v1 + v2;
    __syncthreads();
    #pragma unroll
    for (int s = 128; s > 0; s >>= 1) { if (tid < s) red[tid] += red[tid + s]; __syncthreads(); }
    float mean = red[0] * (1.0f / Dm);
    __syncthreads();
    float d0 = v0 - mean, d1 = v1 - mean, d2 = v2 - mean;
    red[tid] = d0 * d0 + d1 * d1 + d2 * d2;
    __syncthreads();
    #pragma unroll
    for (int s = 128; s > 0; s >>= 1) { if (tid < s) red[tid] += red[tid + s]; __syncthreads(); }
    float rstd = rsqrtf(red[0] * (1.0f / Dm) + 1e-5f);
    size_t base = (size_t)row * Dm;
    #pragma unroll
    for (int j = 0; j < 3; j++) {
        int i = tid + j * 256;
        float dd = (j == 0) ? d0 : (j == 1) ? d1 : d2;
        float v = dd * rstd * g[i] + b[i];
        __nv_bfloat16 h = __float2bfloat16(v);
        ohi[base + i] = h;
        olo[base + i] = __float2bfloat16(v - __bfloat162float(h));
    }
}

// ---------------- weight transpose + hi/lo split: W[K,N] -> out[N,K] ----------------
__global__ void wconvT_kernel(const float* __restrict__ W,
                              __nv_bfloat16* __restrict__ hi,
                              __nv_bfloat16* __restrict__ lo,
                              int K, int N) {
    __shared__ float t[32][33];
    size_t zoff = (size_t)blockIdx.z * K * N;
    const float* Wl = W + zoff;
    int n0 = blockIdx.x * 32, k0 = blockIdx.y * 32;
    int tx = threadIdx.x, ty = threadIdx.y;
    for (int i = ty; i < 32; i += 8)
        t[i][tx] = Wl[(size_t)(k0 + i) * N + n0 + tx];
    __syncthreads();
    for (int i = ty; i < 32; i += 8) {
        float v = t[tx][i];  // = W[k0+tx][n0+i]
        __nv_bfloat16 h = __float2bfloat16(v);
        size_t o = zoff + (size_t)(n0 + i) * K + k0 + tx;
        hi[o] = h;
        lo[o] = __float2bfloat16(v - __bfloat162float(h));
    }
}

__global__ void wte_conv_kernel(const float* __restrict__ W,
                                __nv_bfloat16* __restrict__ hi,
                                __nv_bfloat16* __restrict__ lo, int n) {
    int i = blockIdx.x * 256 + threadIdx.x;
    if (i < n) {
        float v = W[i];
        __nv_bfloat16 h = __float2bfloat16(v);
        hi[i] = h;
        lo[i] = __float2bfloat16(v - __bfloat162float(h));
    }
}

// ---------------- HMMA GEMM (merged 3-term split): C = (Ahi+Alo)(Bhi+Blo)^T ----------------
// CTA tile 128x128, K-chunk 64. Per stage smem holds Ahi|Alo|Bhi|Blo (4 x 16KB = 64KB).
// 3 stages (192 KB), 1 CTA/SM, 8 warps (2m x 4n), warp tile 64x32.
// Per ks: load frags once, issue ahi*bhi + alo*bhi + ahi*blo into same fp32 acc.
// EPI: 0 = +bias -> fp32 | 1 = +bias+res -> fp32 | 2 = +bias,gelu -> bf16 hi/lo | 3 = plain fp32
#define GSMEM 196608

template<int EPI, bool GUARD>
__global__ __launch_bounds__(256, 1) void mm_gemm(
    const __nv_bfloat16* __restrict__ Ahi, const __nv_bfloat16* __restrict__ Alo,
    const __nv_bfloat16* __restrict__ Bhi, const __nv_bfloat16* __restrict__ Blo,
    const float* __restrict__ bias, const float* __restrict__ res,
    float* __restrict__ outF,
    __nv_bfloat16* __restrict__ outHi, __nv_bfloat16* __restrict__ outLo,
    int M, int N, int K)
{
    extern __shared__ char smem[];
    uint32_t sb = smem_u32(smem);
    const int m0 = blockIdx.x * 128;
    const int n0 = blockIdx.y * 128;
    const int tid  = threadIdx.x;
    const int warp = tid >> 5, lane = tid & 31;
    const int wm = warp >> 2, wn = warp & 3;     // 2 x 4 warp grid

    float acc[4][4][4] = {};                      // [mt][nt][frag]
    const int NC = K >> 6;                        // k-chunks of 64

    auto issue = [&](int ch) {
        const uint32_t base = sb + (uint32_t)(ch % 3) * 65536u;
        const size_t koff = (size_t)ch * 64;
        #pragma unroll
        for (int c = 0; c < 4; c++) {             // A hi+lo: 128 rows x 128B each
            int idx = tid + c * 256;
            int r = idx >> 3, g16 = idx & 7;
            size_t go = (size_t)(m0 + r) * K + koff + g16 * 8;
            uint32_t so = SWZ(r * 128 + g16 * 16);
            cpasync16f(base + so,         Ahi + go);
            cpasync16f(base + 16384 + so, Alo + go);
        }
        #pragma unroll
        for (int c = 0; c < 4; c++) {             // B hi+lo: 128 rows x 128B each
            int idx = tid + c * 256;
            int r = idx >> 3, g16 = idx & 7;
            uint32_t so = SWZ(r * 128 + g16 * 16);
            if (GUARD) {
                int n = n0 + r;
                uint32_t ok = (n < N) ? 16u : 0u;
                size_t go = (size_t)((n < N) ? n : 0) * K + koff + g16 * 8;
                cpasync16(base + 32768 + so, Bhi + go, ok);
                cpasync16(base + 49152 + so, Blo + go, ok);
            } else {
                size_t go = (size_t)(n0 + r) * K + koff + g16 * 8;
                cpasync16f(base + 32768 + so, Bhi + go);
                cpasync16f(base + 49152 + so, Blo + go);
            }
        }
        cp_commit();
    };

    issue(0);
    if (NC > 1) issue(1);
    for (int it = 0; it < NC; ++it) {
        cp_wait1();            // chunk it complete (only it+1 may remain)
        __syncthreads();       // all warps see stage data; all done reading stage it-1
        if (it + 2 < NC) issue(it + 2);

        const uint32_t aHi = sb + (uint32_t)(it % 3) * 65536u;
        const uint32_t aLo = aHi + 16384;
        const uint32_t bHi = aHi + 32768;
        const uint32_t bLo = aHi + 49152;
        #pragma unroll
        for (int ks = 0; ks < 4; ks++) {
            uint32_t ahi[4][4], alo[4][4], bhi[4][2], blo[4][2];
            #pragma unroll
            for (int mt = 0; mt < 4; mt++) {
                uint32_t so = SWZ((wm * 64 + mt * 16 + (lane & 15)) * 128 + ks * 32 + (lane >> 4) * 16);
                ldsm4(ahi[mt], aHi + so);
                ldsm4(alo[mt], aLo + so);
            }
            #pragma unroll
            for (int p = 0; p < 2; p++) {        // two n-tiles per ldsm.x4
                int q = lane >> 3;
                uint32_t so = SWZ((wn * 32 + p * 16 + (q >> 1) * 8 + (lane & 7)) * 128 + ks * 32 + (q & 1) * 16);
                uint32_t t4[4];
                ldsm4(t4, bHi + so);
                bhi[2 * p][0] = t4[0]; bhi[2 * p][1] = t4[1];
                bhi[2 * p + 1][0] = t4[2]; bhi[2 * p + 1][1] = t4[3];
                ldsm4(t4, bLo + so);
                blo[2 * p][0] = t4[0]; blo[2 * p][1] = t4[1];
                blo[2 * p + 1][0] = t4[2]; blo[2 * p + 1][1] = t4[3];
            }
            #pragma unroll
            for (int mt = 0; mt < 4; mt++)
                #pragma unroll
                for (int nt = 0; nt < 4; nt++)
                    mma16816(acc[mt][nt], ahi[mt], bhi[nt]);
            #pragma unroll
            for (int mt = 0; mt < 4; mt++)
                #pragma unroll
                for (int nt = 0; nt < 4; nt++)
                    mma16816(acc[mt][nt], alo[mt], bhi[nt]);
            #pragma unroll
            for (int mt = 0; mt < 4; mt++)
                #pragma unroll
                for (int nt = 0; nt < 4; nt++)
                    mma16816(acc[mt][nt], ahi[mt], blo[nt]);
        }
    }

    // ---------------- epilogue: direct register -> global ----------------
    const int g = lane >> 2, tig = lane & 3;
    #pragma unroll
    for (int mt = 0; mt < 4; mt++) {
        #pragma unroll
        for (int nt = 0; nt < 4; nt++) {
            int nc = n0 + wn * 32 + nt * 8 + tig * 2;
            #pragma unroll
            for (int h = 0; h < 2; h++) {       // row g / row g+8
                int m = m0 + wm * 64 + mt * 16 + g + h * 8;
                float v0 = acc[mt][nt][2 * h];
                float v1 = acc[mt][nt][2 * h + 1];
                size_t gi = (size_t)m * N + nc;
                if (EPI == 3) {
                    if (!GUARD || nc < N)     outF[gi]     = v0;
                    if (!GUARD || nc + 1 < N) outF[gi + 1] = v1;
                } else {
                    v0 += bias[nc]; v1 += bias[nc + 1];
                    if (EPI == 2) {
                        v0 *= normcdff(v0); v1 *= normcdff(v1);
                        __nv_bfloat16 h0 = __float2bfloat16(v0);
                        __nv_bfloat16 h1 = __float2bfloat16(v1);
                        __nv_bfloat162 hv; hv.x = h0; hv.y = h1;
                        __nv_bfloat162 lv;
                        lv.x = __float2bfloat16(v0 - __bfloat162float(h0));
                        lv.y = __float2bfloat16(v1 - __bfloat162float(h1));
                        *reinterpret_cast<__nv_bfloat162*>(outHi + gi) = hv;
                        *reinterpret_cast<__nv_bfloat162*>(outLo + gi) = lv;
                    } else {
                        if (EPI == 1) {
                            float2 r2 = *reinterpret_cast<const float2*>(res + gi);
                            v0 += r2.x; v1 += r2.y;
                        }
                        float2 o2; o2.x = v0; o2.y = v1;
                        *reinterpret_cast<float2*>(outF + gi) = o2;
                    }
                }
            }
        }
    }
}

// ---------------- attention: 16 queries / block, 256 threads, bf16 hi/lo out ----------------
// dynamic smem layout: sc[QT][1040] | qs[QT][64] | part[4][QT][64] | red[QT*8]
#define ASC_STRIDE 1040
#define ASMEM ((QT*ASC_STRIDE + QT*64 + 4*QT*64 + QT*8) * 4)

__global__ __launch_bounds__(256, 2) void attn_kernel(const float* __restrict__ qkv,
                                                      __nv_bfloat16* __restrict__ ohi,
                                                      __nv_bfloat16* __restrict__ olo) {
    extern __shared__ float As[];
    float* sc   = As;                              // [QT][ASC_STRIDE]
    float* qs   = As + QT * ASC_STRIDE;            // [QT][64]
    float* part = qs + QT * 64;                    // [4][QT][64]
    float* red  = part + 4 * QT * 64;              // [QT][8]
    __shared__ float mxs[QT], sms[QT];

    const int q0  = blockIdx.x * QT;
    const int n   = blockIdx.y;
    const int b   = blockIdx.z;
    const int tid = threadIdx.x;
    const int lane = tid & 31, warp = tid >> 5;

    const float* base = qkv + (size_t)b * Tlen * (3 * Dm);

    for (int i = tid; i < QT * 64; i += 256) {
        int qq = i >> 6, d = i & 63;
        qs[qq * 64 + d] = base[(size_t)(q0 + qq) * (3 * Dm) + n * 64 + d];
    }
    __syncthreads();

    const int kmax = q0 + QT - 1;

    // ---- phase 1: scores + local max ----
    float lm[QT];
    #pragma unroll
    for (int qq = 0; qq < QT; qq++) lm[qq] = -1e30f;
    for (int k = tid; k <= kmax; k += 256) {
        const float* kr = base + (size_t)k * (3 * Dm) + Dm + n * 64;
        float s[QT];
        #pragma unroll
        for (int qq = 0; qq < QT; qq++) s[qq] = 0.f;
        #pragma unroll
        for (int d = 0; d < 64; d += 4) {
            float4 kv = *(const float4*)(kr + d);
            #pragma unroll
            for (int qq = 0; qq < QT; qq++) {
                float4 qv = *(const float4*)(qs + qq * 64 + d);
                s[qq] += kv.x * qv.x + kv.y * qv.y + kv.z * qv.z + kv.w * qv.w;
            }
        }
        #pragma unroll
        for (int qq = 0; qq < QT; qq++) {
            float sv = (k <= q0 + qq) ? s[qq] * 0.125f : -1e30f;
            sc[qq * ASC_STRIDE + k] = sv;
            lm[qq] = fmaxf(lm[qq], sv);
        }
    }
    #pragma unroll
    for (int qq = 0; qq < QT; qq++) {
        #pragma unroll
        for (int o = 16; o > 0; o >>= 1)
            lm[qq] = fmaxf(lm[qq], __shfl_xor_sync(0xffffffffu, lm[qq], o));
    }
    if (lane == 0) {
        #pragma unroll
        for (int qq = 0; qq < QT; qq++) red[qq * 8 + warp] = lm[qq];
    }
    __syncthreads();
    if (tid < QT) {
        float m = -1e30f;
        #pragma unroll
        for (int w = 0; w < 8; w++) m = fmaxf(m, red[tid * 8 + w]);
        mxs[tid] = m;
    }
    __syncthreads();

    // ---- phase 2: exp + local sum ----
    float mx[QT];
    #pragma unroll
    for (int qq = 0; qq < QT; qq++) mx[qq] = mxs[qq];
    float ls[QT];
    #pragma unroll
    for (int qq = 0; qq < QT; qq++) ls[qq] = 0.f;
    for (int k = tid; k <= kmax; k += 256) {
        #pragma unroll
        for (int qq = 0; qq < QT; qq++) {
            float e = __expf(sc[qq * ASC_STRIDE + k] - mx[qq]);
            sc[qq * ASC_STRIDE + k] = e;
            ls[qq] += e;
        }
    }
    #pragma unroll
    for (int qq = 0; qq < QT; qq++) {
        #pragma unroll
        for (int o = 16; o > 0; o >>= 1)
            ls[qq] += __shfl_xor_sync(0xffffffffu, ls[qq], o);
    }
    if (lane == 0) {
        #pragma unroll
        for (int qq = 0; qq < QT; qq++) red[qq * 8 + warp] = ls[qq];
    }
    __syncthreads();
    if (tid < QT) {
        float s = 0.f;
        #pragma unroll
        for (int w = 0; w < 8; w++) s += red[tid * 8 + w];
        sms[tid] = s;
    }
    __syncthreads();

    // ---- phase 3: o = P @ V ----
    {
        const int d = tid & 63, h = tid >> 6;     // 4 k-slices
        const int kcount = q0 + QT;               // multiple of 16
        const int chunk  = kcount >> 2;           // multiple of 4
        const int klo = h * chunk, khi = klo + chunk;
        float a[QT];
        #pragma unroll
        for (int qq = 0; qq < QT; qq++) a[qq] = 0.f;
        const float* vb = base + 2 * Dm + n * 64 + d;
        for (int k = klo; k < khi; k += 4) {
            float vv0 = vb[(size_t)(k + 0) * (3 * Dm)];
            float vv1 = vb[(size_t)(k + 1) * (3 * Dm)];
            float vv2 = vb[(size_t)(k + 2) * (3 * Dm)];
            float vv3 = vb[(size_t)(k + 3) * (3 * Dm)];
            #pragma unroll
            for (int qq = 0; qq < QT; qq++) {
                float4 p = *(const float4*)(sc + qq * ASC_STRIDE + k);
                a[qq] += p.x * vv0 + p.y * vv1 + p.z * vv2 + p.w * vv3;
            }
        }
        #pragma unroll
        for (int qq = 0; qq < QT; qq++) part[(h * QT + qq) * 64 + d] = a[qq];
        __syncthreads();
        if (h == 0) {
            #pragma unroll
            for (int qq = 0; qq < QT; qq++) {
                float o = (part[(0 * QT + qq) * 64 + d] + part[(1 * QT + qq) * 64 + d]
                         + part[(2 * QT + qq) * 64 + d] + part[(3 * QT + qq) * 64 + d]) / sms[qq];
                size_t gi = (size_t)(b * Tlen + q0 + qq) * Dm + n * 64 + d;
                __nv_bfloat16 hh = __float2bfloat16(o);
                ohi[gi] = hh;
                olo[gi] = __float2bfloat16(o - __bfloat162float(hh));
            }
        }
    }
}

// ---------------- host driver ----------------
extern "C" void kernel_launch(void* const* d_in, const int* in_sizes, int n_in,
                              void* d_out, int out_size) {
    const int*   tokens      = (const int*)  d_in[0];
    const float* wte         = (const float*)d_in[1];
    const float* wpe         = (const float*)d_in[2];
    const float* ln1_g       = (const float*)d_in[3];
    const float* ln1_b       = (const float*)d_in[4];
    const float* attn_w      = (const float*)d_in[5];
    const float* attn_b      = (const float*)d_in[6];
    const float* attn_proj_w = (const float*)d_in[7];
    const float* attn_proj_b = (const float*)d_in[8];
    const float* ln2_g       = (const float*)d_in[9];
    const float* ln2_b       = (const float*)d_in[10];
    const float* fc_w        = (const float*)d_in[11];
    const float* fc_b        = (const float*)d_in[12];
    const float* mlp_proj_w  = (const float*)d_in[13];
    const float* mlp_proj_b  = (const float*)d_in[14];
    const float* lnf_g       = (const float*)d_in[15];
    const float* lnf_b       = (const float*)d_in[16];
    float* out = (float*)d_out;

    float *xp, *qkvp;
    __nv_bfloat16 *hhi, *hlo, *ahi, *alo, *fchi, *fclo;
    __nv_bfloat16 *qh, *ql, *aph, *apl, *fch, *fcl, *mph, *mpl, *teh, *tel;
    cudaGetSymbolAddress((void**)&xp,   g_x);
    cudaGetSymbolAddress((void**)&qkvp, g_qkv);
    cudaGetSymbolAddress((void**)&hhi,  g_hhi);  cudaGetSymbolAddress((void**)&hlo,  g_hlo);
    cudaGetSymbolAddress((void**)&ahi,  g_ahi);  cudaGetSymbolAddress((void**)&alo,  g_alo);
    cudaGetSymbolAddress((void**)&fchi, g_fchi); cudaGetSymbolAddress((void**)&fclo, g_fclo);
    cudaGetSymbolAddress((void**)&qh,  w_qkv_hi); cudaGetSymbolAddress((void**)&ql,  w_qkv_lo);
    cudaGetSymbolAddress((void**)&aph, w_ap_hi);  cudaGetSymbolAddress((void**)&apl, w_ap_lo);
    cudaGetSymbolAddress((void**)&fch, w_fc_hi);  cudaGetSymbolAddress((void**)&fcl, w_fc_lo);
    cudaGetSymbolAddress((void**)&mph, w_mp_hi);  cudaGetSymbolAddress((void**)&mpl, w_mp_lo);
    cudaGetSymbolAddress((void**)&teh, w_te_hi);  cudaGetSymbolAddress((void**)&tel, w_te_lo);

    cudaFuncSetAttribute((const void*)mm_gemm<0,false>, cudaFuncAttributeMaxDynamicSharedMemorySize, GSMEM);
    cudaFuncSetAttribute((const void*)mm_gemm<1,false>, cudaFuncAttributeMaxDynamicSharedMemorySize, GSMEM);
    cudaFuncSetAttribute((const void*)mm_gemm<2,false>, cudaFuncAttributeMaxDynamicSharedMemorySize, GSMEM);
    cudaFuncSetAttribute((const void*)mm_gemm<3,true >, cudaFuncAttributeMaxDynamicSharedMemorySize, GSMEM);
    cudaFuncSetAttribute((const void*)attn_kernel, cudaFuncAttributeMaxDynamicSharedMemorySize, ASMEM);

    // weight conversion (transpose + hi/lo split) every call (deterministic)
    dim3 wb(32, 8);
    wconvT_kernel<<<dim3(3*Dm/32, Dm/32, Lc), wb>>>(attn_w,      qh,  ql,  Dm, 3*Dm);
    wconvT_kernel<<<dim3(Dm/32,   Dm/32, Lc), wb>>>(attn_proj_w, aph, apl, Dm, Dm);
    wconvT_kernel<<<dim3(Fm/32,   Dm/32, Lc), wb>>>(fc_w,        fch, fcl, Dm, Fm);
    wconvT_kernel<<<dim3(Dm/32,   Fm/32, Lc), wb>>>(mlp_proj_w,  mph, mpl, Fm, Dm);
    wte_conv_kernel<<<(Vv*Dm + 255)/256, 256>>>(wte, teh, tel, Vv*Dm);

    embed_kernel<<<Rows, 256>>>(tokens, wte, wpe, xp);

    const dim3 gQKV(Rows/128, (3*Dm)/128);
    const dim3 gP  (Rows/128, Dm/128);
    const dim3 gF  (Rows/128, Fm/128);
    const dim3 gV  (Rows/128, (Vv + 127)/128);
    const dim3 gAtt(Tlen/QT, Nh, Bsz);

    for (int l = 0; l < Lc; l++) {
        ln_kernel<<<Rows, 256>>>(xp, ln1_g + l*Dm, ln1_b + l*Dm, hhi, hlo);
        mm_gemm<0,false><<<gQKV, 256, GSMEM>>>(hhi, hlo,
            qh + (size_t)l*3*Dm*Dm, ql + (size_t)l*3*Dm*Dm,
            attn_b + (size_t)l*3*Dm, nullptr, qkvp, nullptr, nullptr,
            Rows, 3*Dm, Dm);
        attn_kernel<<<gAtt, 256, ASMEM>>>(qkvp, ahi, alo);
        mm_gemm<1,false><<<gP, 256, GSMEM>>>(ahi, alo,
            aph + (size_t)l*Dm*Dm, apl + (size_t)l*Dm*Dm,
            attn_proj_b + (size_t)l*Dm, xp, xp, nullptr, nullptr,
            Rows, Dm, Dm);
        ln_kernel<<<Rows, 256>>>(xp, ln2_g + l*Dm, ln2_b + l*Dm, hhi, hlo);
        mm_gemm<2,false><<<gF, 256, GSMEM>>>(hhi, hlo,
            fch + (size_t)l*Fm*Dm, fcl + (size_t)l*Fm*Dm,
            fc_b + (size_t)l*Fm, nullptr, nullptr, fchi, fclo,
            Rows, Fm, Dm);
        mm_gemm<1,false><<<gP, 256, GSMEM>>>(fchi, fclo,
            mph + (size_t)l*Dm*Fm, mpl + (size_t)l*Dm*Fm,
            mlp_proj_b + (size_t)l*Dm, xp, xp, nullptr, nullptr,
            Rows, Dm, Fm);
    }

    ln_kernel<<<Rows, 256>>>(xp, lnf_g, lnf_b, hhi, hlo);
    mm_gemm<3,true><<<gV, 256, GSMEM>>>(hhi, hlo, teh, tel,
        nullptr, nullptr, out, nullptr, nullptr,
        Rows, Vv, Dm);
}

// round 6
// speedup vs baseline: 3.5913x; 1.2467x over previous
#include <cuda_runtime.h>
#include <cuda_fp16.h>
#include <math.h>
#include <stdint.h>

#define Bsz 4
#define Tlen 1024
#define Dm 768
#define Nh 12
#define Fm 3072
#define Lc 12
#define Vv 50257
#define Rows (Bsz*Tlen)   /* 4096 */
#define QT 16             /* attention queries per block */

// ---------------- scratch (static device globals; no allocation) ----------------
__device__ float g_x[Rows*Dm];                       // residual stream (fp32)
__device__ __half g_hhi[Rows*Dm], g_hlo[Rows*Dm];    // LN output hi/lo (f16)
__device__ float g_qkv[Rows*3*Dm];
__device__ __half g_ahi[Rows*Dm], g_alo[Rows*Dm];    // attn out hi/lo
__device__ __half g_fchi[Rows*Fm], g_fclo[Rows*Fm];  // gelu(fc) hi/lo
// transposed weights [N,K], single f16
__device__ __half w_qkv[Lc*3*Dm*Dm];
__device__ __half w_ap [Lc*Dm*Dm];
__device__ __half w_fc [Lc*Fm*Dm];
__device__ __half w_mp [Lc*Dm*Fm];
__device__ __half w_te [Vv*Dm];

// ---------------- helpers ----------------
__device__ __forceinline__ uint32_t smem_u32(const void* p) {
    uint32_t a;
    asm("{ .reg .u64 t; cvta.to.shared.u64 t, %1; cvt.u32.u64 %0, t; }" : "=r"(a) : "l"(p));
    return a;
}
#define SWZ(o) ((o) ^ ((((uint32_t)(o)) >> 3) & 0x70))

__device__ __forceinline__ void cpasync16(uint32_t s, const void* g, uint32_t sz) {
    asm volatile("cp.async.cg.shared.global [%0], [%1], 16, %2;\n"
                 :: "r"(s), "l"(g), "r"(sz) : "memory");
}
__device__ __forceinline__ void cpasync16f(uint32_t s, const void* g) {
    asm volatile("cp.async.cg.shared.global [%0], [%1], 16;\n"
                 :: "r"(s), "l"(g) : "memory");
}
__device__ __forceinline__ void cp_commit() {
    asm volatile("cp.async.commit_group;\n" ::: "memory");
}
__device__ __forceinline__ void cp_wait2() {
    asm volatile("cp.async.wait_group 2;\n" ::: "memory");
}
__device__ __forceinline__ void ldsm4(uint32_t r[4], uint32_t addr) {
    asm volatile("ldmatrix.sync.aligned.m8n8.x4.shared.b16 {%0,%1,%2,%3}, [%4];"
                 : "=r"(r[0]), "=r"(r[1]), "=r"(r[2]), "=r"(r[3]) : "r"(addr));
}
__device__ __forceinline__ void mma16816(float c[4], const uint32_t a[4], const uint32_t b[2]) {
    asm volatile("mma.sync.aligned.m16n8k16.row.col.f32.f16.f16.f32 "
                 "{%0,%1,%2,%3}, {%4,%5,%6,%7}, {%8,%9}, {%0,%1,%2,%3};"
                 : "+f"(c[0]), "+f"(c[1]), "+f"(c[2]), "+f"(c[3])
                 : "r"(a[0]), "r"(a[1]), "r"(a[2]), "r"(a[3]), "r"(b[0]), "r"(b[1]));
}

// ---------------- embedding ----------------
__global__ void embed_kernel(const int* __restrict__ tokens,
                             const float* __restrict__ wte,
                             const float* __restrict__ wpe,
                             float* __restrict__ x) {
    int row = blockIdx.x;
    int t   = row % Tlen;
    int tok = tokens[row];
    const float* we = wte + (size_t)tok * Dm;
    const float* pe = wpe + (size_t)t   * Dm;
    float* xr = x + (size_t)row * Dm;
    for (int i = threadIdx.x; i < Dm; i += blockDim.x)
        xr[i] = we[i] + pe[i];
}

// ---------------- layernorm -> f16 hi/lo ----------------
__global__ void ln_kernel(const float* __restrict__ x,
                          const float* __restrict__ g,
                          const float* __restrict__ b,
                          __half* __restrict__ ohi,
                          __half* __restrict__ olo) {
    int row = blockIdx.x;
    int tid = threadIdx.x;
    const float* xr = x + (size_t)row * Dm;
    float v0 = xr[tid], v1 = xr[tid + 256], v2 = xr[tid + 512];
    __shared__ float red[256];
    red[tid] = v0 + v1 + v2;
    __syncthreads();
    #pragma unroll
    for (int s = 128; s > 0; s >>= 1) { if (tid < s) red[tid] += red[tid + s]; __syncthreads(); }
    float mean = red[0] * (1.0f / Dm);
    __syncthreads();
    float d0 = v0 - mean, d1 = v1 - mean, d2 = v2 - mean;
    red[tid] = d0 * d0 + d1 * d1 + d2 * d2;
    __syncthreads();
    #pragma unroll
    for (int s = 128; s > 0; s >>= 1) { if (tid < s) red[tid] += red[tid + s]; __syncthreads(); }
    float rstd = rsqrtf(red[0] * (1.0f / Dm) + 1e-5f);
    size_t base = (size_t)row * Dm;
    #pragma unroll
    for (int j = 0; j < 3; j++) {
        int i = tid + j * 256;
        float dd = (j == 0) ? d0 : (j == 1) ? d1 : d2;
        float v = dd * rstd * g[i] + b[i];
        __half h = __float2half_rn(v);
        ohi[base + i] = h;
        olo[base + i] = __float2half_rn(v - __half2float(h));
    }
}

// ---------------- weight transpose + f16: W[K,N] -> out[N,K] ----------------
__global__ void wconvT_kernel(const float* __restrict__ W,
                              __half* __restrict__ hi,
                              int K, int N) {
    __shared__ float t[32][33];
    size_t zoff = (size_t)blockIdx.z * K * N;
    const float* Wl = W + zoff;
    int n0 = blockIdx.x * 32, k0 = blockIdx.y * 32;
    int tx = threadIdx.x, ty = threadIdx.y;
    for (int i = ty; i < 32; i += 8)
        t[i][tx] = Wl[(size_t)(k0 + i) * N + n0 + tx];
    __syncthreads();
    for (int i = ty; i < 32; i += 8) {
        float v = t[tx][i];  // = W[k0+tx][n0+i]
        hi[zoff + (size_t)(n0 + i) * K + k0 + tx] = __float2half_rn(v);
    }
}

__global__ void wte_conv_kernel(const float* __restrict__ W,
                                __half* __restrict__ hi, int n) {
    int i = blockIdx.x * 256 + threadIdx.x;
    if (i < n) hi[i] = __float2half_rn(W[i]);
}

// ---------------- HMMA GEMM (2-term f16 split): C = (Ahi+Alo)[M,K] @ B[N,K]^T ----------------
// CTA tile 128x128, K-chunk 64. Per stage smem: Ahi|Alo|B (3 x 16KB = 48KB).
// 4 stages (192 KB), 1 CTA/SM, 8 warps (2m x 4n), warp tile 64x32.
// EPI: 0 = +bias -> fp32 | 1 = +bias+res -> fp32 | 2 = +bias,gelu -> f16 hi/lo | 3 = plain fp32
#define GSMEM 196608

template<int EPI, bool GUARD>
__global__ __launch_bounds__(256, 1) void mm_gemm(
    const __half* __restrict__ Ahi, const __half* __restrict__ Alo,
    const __half* __restrict__ B,
    const float* __restrict__ bias, const float* __restrict__ res,
    float* __restrict__ outF,
    __half* __restrict__ outHi, __half* __restrict__ outLo,
    int M, int N, int K)
{
    extern __shared__ char smem[];
    uint32_t sb = smem_u32(smem);
    const int m0 = blockIdx.x * 128;
    const int n0 = blockIdx.y * 128;
    const int tid  = threadIdx.x;
    const int warp = tid >> 5, lane = tid & 31;
    const int wm = warp >> 2, wn = warp & 3;     // 2 x 4 warp grid

    float acc[4][4][4] = {};                      // [mt][nt][frag]
    const int NC = K >> 6;                        // k-chunks of 64

    auto issue = [&](int ch) {
        const uint32_t base = sb + (uint32_t)(ch & 3) * 49152u;
        const size_t koff = (size_t)ch * 64;
        #pragma unroll
        for (int c = 0; c < 4; c++) {             // A hi+lo: 128 rows x 128B each
            int idx = tid + c * 256;
            int r = idx >> 3, g16 = idx & 7;
            size_t go = (size_t)(m0 + r) * K + koff + g16 * 8;
            uint32_t so = SWZ(r * 128 + g16 * 16);
            cpasync16f(base + so,         Ahi + go);
            cpasync16f(base + 16384 + so, Alo + go);
        }
        #pragma unroll
        for (int c = 0; c < 4; c++) {             // B: 128 rows x 128B
            int idx = tid + c * 256;
            int r = idx >> 3, g16 = idx & 7;
            uint32_t so = SWZ(r * 128 + g16 * 16);
            if (GUARD) {
                int n = n0 + r;
                uint32_t ok = (n < N) ? 16u : 0u;
                cpasync16(base + 32768 + so,
                          B + (size_t)((n < N) ? n : 0) * K + koff + g16 * 8, ok);
            } else {
                cpasync16f(base + 32768 + so,
                           B + (size_t)(n0 + r) * K + koff + g16 * 8);
            }
        }
        cp_commit();
    };

    issue(0);
    if (NC > 1) issue(1);
    if (NC > 2) issue(2);
    for (int it = 0; it < NC; ++it) {
        cp_wait2();            // chunk it complete (up to it+1, it+2 may remain)
        __syncthreads();       // all warps see stage data; all done reading stage it-1
        if (it + 3 < NC) issue(it + 3);   // overwrites stage (it-1)&3 — safe after sync

        const uint32_t aHi = sb + (uint32_t)(it & 3) * 49152u;
        const uint32_t aLo = aHi + 16384;
        const uint32_t bBs = aHi + 32768;
        #pragma unroll
        for (int ks = 0; ks < 4; ks++) {
            uint32_t ahi[4][4], alo[4][4], b[4][2];
            #pragma unroll
            for (int mt = 0; mt < 4; mt++) {
                uint32_t so = SWZ((wm * 64 + mt * 16 + (lane & 15)) * 128 + ks * 32 + (lane >> 4) * 16);
                ldsm4(ahi[mt], aHi + so);
                ldsm4(alo[mt], aLo + so);
            }
            #pragma unroll
            for (int p = 0; p < 2; p++) {        // two n-tiles per ldsm.x4
                int q = lane >> 3;
                uint32_t so = SWZ((wn * 32 + p * 16 + (q >> 1) * 8 + (lane & 7)) * 128 + ks * 32 + (q & 1) * 16);
                uint32_t t4[4];
                ldsm4(t4, bBs + so);
                b[2 * p][0] = t4[0]; b[2 * p][1] = t4[1];
                b[2 * p + 1][0] = t4[2]; b[2 * p + 1][1] = t4[3];
            }
            #pragma unroll
            for (int mt = 0; mt < 4; mt++)
                #pragma unroll
                for (int nt = 0; nt < 4; nt++)
                    mma16816(acc[mt][nt], ahi[mt], b[nt]);
            #pragma unroll
            for (int mt = 0; mt < 4; mt++)
                #pragma unroll
                for (int nt = 0; nt < 4; nt++)
                    mma16816(acc[mt][nt], alo[mt], b[nt]);
        }
    }

    // ---------------- epilogue: direct register -> global ----------------
    const int g = lane >> 2, tig = lane & 3;
    #pragma unroll
    for (int mt = 0; mt < 4; mt++) {
        #pragma unroll
        for (int nt = 0; nt < 4; nt++) {
            int nc = n0 + wn * 32 + nt * 8 + tig * 2;
            #pragma unroll
            for (int h = 0; h < 2; h++) {       // row g / row g+8
                int m = m0 + wm * 64 + mt * 16 + g + h * 8;
                float v0 = acc[mt][nt][2 * h];
                float v1 = acc[mt][nt][2 * h + 1];
                size_t gi = (size_t)m * N + nc;
                if (EPI == 3) {
                    if (!GUARD || nc < N)     outF[gi]     = v0;
                    if (!GUARD || nc + 1 < N) outF[gi + 1] = v1;
                } else {
                    v0 += bias[nc]; v1 += bias[nc + 1];
                    if (EPI == 2) {
                        v0 *= normcdff(v0); v1 *= normcdff(v1);
                        __half h0 = __float2half_rn(v0);
                        __half h1 = __float2half_rn(v1);
                        __half2 hv; hv.x = h0; hv.y = h1;
                        __half2 lv;
                        lv.x = __float2half_rn(v0 - __half2float(h0));
                        lv.y = __float2half_rn(v1 - __half2float(h1));
                        *reinterpret_cast<__half2*>(outHi + gi) = hv;
                        *reinterpret_cast<__half2*>(outLo + gi) = lv;
                    } else {
                        if (EPI == 1) {
                            float2 r2 = *reinterpret_cast<const float2*>(res + gi);
                            v0 += r2.x; v1 += r2.y;
                        }
                        float2 o2; o2.x = v0; o2.y = v1;
                        *reinterpret_cast<float2*>(outF + gi) = o2;
                    }
                }
            }
        }
    }
}

// ---------------- attention: 16 queries / block, 256 threads, f16 hi/lo out ----------------
// dynamic smem layout: sc[QT][1040] | qs[QT][64] | part[4][QT][64] | red[QT*8]
#define ASC_STRIDE 1040
#define ASMEM ((QT*ASC_STRIDE + QT*64 + 4*QT*64 + QT*8) * 4)

__global__ __launch_bounds__(256, 2) void attn_kernel(const float* __restrict__ qkv,
                                                      __half* __restrict__ ohi,
                                                      __half* __restrict__ olo) {
    extern __shared__ float As[];
    float* sc   = As;                              // [QT][ASC_STRIDE]
    float* qs   = As + QT * ASC_STRIDE;            // [QT][64]
    float* part = qs + QT * 64;                    // [4][QT][64]
    float* red  = part + 4 * QT * 64;              // [QT][8]
    __shared__ float mxs[QT], sms[QT];

    const int q0  = blockIdx.x * QT;
    const int n   = blockIdx.y;
    const int b   = blockIdx.z;
    const int tid = threadIdx.x;
    const int lane = tid & 31, warp = tid >> 5;

    const float* base = qkv + (size_t)b * Tlen * (3 * Dm);

    for (int i = tid; i < QT * 64; i += 256) {
        int qq = i >> 6, d = i & 63;
        qs[qq * 64 + d] = base[(size_t)(q0 + qq) * (3 * Dm) + n * 64 + d];
    }
    __syncthreads();

    const int kmax = q0 + QT - 1;

    // ---- phase 1: scores + local max ----
    float lm[QT];
    #pragma unroll
    for (int qq = 0; qq < QT; qq++) lm[qq] = -1e30f;
    for (int k = tid; k <= kmax; k += 256) {
        const float* kr = base + (size_t)k * (3 * Dm) + Dm + n * 64;
        float s[QT];
        #pragma unroll
        for (int qq = 0; qq < QT; qq++) s[qq] = 0.f;
        #pragma unroll
        for (int d = 0; d < 64; d += 4) {
            float4 kv = *(const float4*)(kr + d);
            #pragma unroll
            for (int qq = 0; qq < QT; qq++) {
                float4 qv = *(const float4*)(qs + qq * 64 + d);
                s[qq] += kv.x * qv.x + kv.y * qv.y + kv.z * qv.z + kv.w * qv.w;
            }
        }
        #pragma unroll
        for (int qq = 0; qq < QT; qq++) {
            float sv = (k <= q0 + qq) ? s[qq] * 0.125f : -1e30f;
            sc[qq * ASC_STRIDE + k] = sv;
            lm[qq] = fmaxf(lm[qq], sv);
        }
    }
    #pragma unroll
    for (int qq = 0; qq < QT; qq++) {
        #pragma unroll
        for (int o = 16; o > 0; o >>= 1)
            lm[qq] = fmaxf(lm[qq], __shfl_xor_sync(0xffffffffu, lm[qq], o));
    }
    if (lane == 0) {
        #pragma unroll
        for (int qq = 0; qq < QT; qq++) red[qq * 8 + warp] = lm[qq];
    }
    __syncthreads();
    if (tid < QT) {
        float m = -1e30f;
        #pragma unroll
        for (int w = 0; w < 8; w++) m = fmaxf(m, red[tid * 8 + w]);
        mxs[tid] = m;
    }
    __syncthreads();

    // ---- phase 2: exp + local sum ----
    float mx[QT];
    #pragma unroll
    for (int qq = 0; qq < QT; qq++) mx[qq] = mxs[qq];
    float ls[QT];
    #pragma unroll
    for (int qq = 0; qq < QT; qq++) ls[qq] = 0.f;
    for (int k = tid; k <= kmax; k += 256) {
        #pragma unroll
        for (int qq = 0; qq < QT; qq++) {
            float e = __expf(sc[qq * ASC_STRIDE + k] - mx[qq]);
            sc[qq * ASC_STRIDE + k] = e;
            ls[qq] += e;
        }
    }
    #pragma unroll
    for (int qq = 0; qq < QT; qq++) {
        #pragma unroll
        for (int o = 16; o > 0; o >>= 1)
            ls[qq] += __shfl_xor_sync(0xffffffffu, ls[qq], o);
    }
    if (lane == 0) {
        #pragma unroll
        for (int qq = 0; qq < QT; qq++) red[qq * 8 + warp] = ls[qq];
    }
    __syncthreads();
    if (tid < QT) {
        float s = 0.f;
        #pragma unroll
        for (int w = 0; w < 8; w++) s += red[tid * 8 + w];
        sms[tid] = s;
    }
    __syncthreads();

    // ---- phase 3: o = P @ V ----
    {
        const int d = tid & 63, h = tid >> 6;     // 4 k-slices
        const int kcount = q0 + QT;               // multiple of 16
        const int chunk  = kcount >> 2;           // multiple of 4
        const int klo = h * chunk, khi = klo + chunk;
        float a[QT];
        #pragma unroll
        for (int qq = 0; qq < QT; qq++) a[qq] = 0.f;
        const float* vb = base + 2 * Dm + n * 64 + d;
        for (int k = klo; k < khi; k += 4) {
            float vv0 = vb[(size_t)(k + 0) * (3 * Dm)];
            float vv1 = vb[(size_t)(k + 1) * (3 * Dm)];
            float vv2 = vb[(size_t)(k + 2) * (3 * Dm)];
            float vv3 = vb[(size_t)(k + 3) * (3 * Dm)];
            #pragma unroll
            for (int qq = 0; qq < QT; qq++) {
                float4 p = *(const float4*)(sc + qq * ASC_STRIDE + k);
                a[qq] += p.x * vv0 + p.y * vv1 + p.z * vv2 + p.w * vv3;
            }
        }
        #pragma unroll
        for (int qq = 0; qq < QT; qq++) part[(h * QT + qq) * 64 + d] = a[qq];
        __syncthreads();
        if (h == 0) {
            #pragma unroll
            for (int qq = 0; qq < QT; qq++) {
                float o = (part[(0 * QT + qq) * 64 + d] + part[(1 * QT + qq) * 64 + d]
                         + part[(2 * QT + qq) * 64 + d] + part[(3 * QT + qq) * 64 + d]) / sms[qq];
                size_t gi = (size_t)(b * Tlen + q0 + qq) * Dm + n * 64 + d;
                __half hh = __float2half_rn(o);
                ohi[gi] = hh;
                olo[gi] = __float2half_rn(o - __half2float(hh));
            }
        }
    }
}

// ---------------- host driver ----------------
extern "C" void kernel_launch(void* const* d_in, const int* in_sizes, int n_in,
                              void* d_out, int out_size) {
    const int*   tokens      = (const int*)  d_in[0];
    const float* wte         = (const float*)d_in[1];
    const float* wpe         = (const float*)d_in[2];
    const float* ln1_g       = (const float*)d_in[3];
    const float* ln1_b       = (const float*)d_in[4];
    const float* attn_w      = (const float*)d_in[5];
    const float* attn_b      = (const float*)d_in[6];
    const float* attn_proj_w = (const float*)d_in[7];
    const float* attn_proj_b = (const float*)d_in[8];
    const float* ln2_g       = (const float*)d_in[9];
    const float* ln2_b       = (const float*)d_in[10];
    const float* fc_w        = (const float*)d_in[11];
    const float* fc_b        = (const float*)d_in[12];
    const float* mlp_proj_w  = (const float*)d_in[13];
    const float* mlp_proj_b  = (const float*)d_in[14];
    const float* lnf_g       = (const float*)d_in[15];
    const float* lnf_b       = (const float*)d_in[16];
    float* out = (float*)d_out;

    float *xp, *qkvp;
    __half *hhi, *hlo, *ahi, *alo, *fchi, *fclo;
    __half *qw, *apw, *fcw, *mpw, *tew;
    cudaGetSymbolAddress((void**)&xp,   g_x);
    cudaGetSymbolAddress((void**)&qkvp, g_qkv);
    cudaGetSymbolAddress((void**)&hhi,  g_hhi);  cudaGetSymbolAddress((void**)&hlo,  g_hlo);
    cudaGetSymbolAddress((void**)&ahi,  g_ahi);  cudaGetSymbolAddress((void**)&alo,  g_alo);
    cudaGetSymbolAddress((void**)&fchi, g_fchi); cudaGetSymbolAddress((void**)&fclo, g_fclo);
    cudaGetSymbolAddress((void**)&qw,  w_qkv);
    cudaGetSymbolAddress((void**)&apw, w_ap);
    cudaGetSymbolAddress((void**)&fcw, w_fc);
    cudaGetSymbolAddress((void**)&mpw, w_mp);
    cudaGetSymbolAddress((void**)&tew, w_te);

    cudaFuncSetAttribute((const void*)mm_gemm<0,false>, cudaFuncAttributeMaxDynamicSharedMemorySize, GSMEM);
    cudaFuncSetAttribute((const void*)mm_gemm<1,false>, cudaFuncAttributeMaxDynamicSharedMemorySize, GSMEM);
    cudaFuncSetAttribute((const void*)mm_gemm<2,false>, cudaFuncAttributeMaxDynamicSharedMemorySize, GSMEM);
    cudaFuncSetAttribute((const void*)mm_gemm<3,true >, cudaFuncAttributeMaxDynamicSharedMemorySize, GSMEM);
    cudaFuncSetAttribute((const void*)attn_kernel, cudaFuncAttributeMaxDynamicSharedMemorySize, ASMEM);

    // weight conversion (transpose + f16) every call (deterministic)
    dim3 wb(32, 8);
    wconvT_kernel<<<dim3(3*Dm/32, Dm/32, Lc), wb>>>(attn_w,      qw,  Dm, 3*Dm);
    wconvT_kernel<<<dim3(Dm/32,   Dm/32, Lc), wb>>>(attn_proj_w, apw, Dm, Dm);
    wconvT_kernel<<<dim3(Fm/32,   Dm/32, Lc), wb>>>(fc_w,        fcw, Dm, Fm);
    wconvT_kernel<<<dim3(Dm/32,   Fm/32, Lc), wb>>>(mlp_proj_w,  mpw, Fm, Dm);
    wte_conv_kernel<<<(Vv*Dm + 255)/256, 256>>>(wte, tew, Vv*Dm);

    embed_kernel<<<Rows, 256>>>(tokens, wte, wpe, xp);

    const dim3 gQKV(Rows/128, (3*Dm)/128);
    const dim3 gP  (Rows/128, Dm/128);
    const dim3 gF  (Rows/128, Fm/128);
    const dim3 gV  (Rows/128, (Vv + 127)/128);
    const dim3 gAtt(Tlen/QT, Nh, Bsz);

    for (int l = 0; l < Lc; l++) {
        ln_kernel<<<Rows, 256>>>(xp, ln1_g + l*Dm, ln1_b + l*Dm, hhi, hlo);
        mm_gemm<0,false><<<gQKV, 256, GSMEM>>>(hhi, hlo,
            qw + (size_t)l*3*Dm*Dm,
            attn_b + (size_t)l*3*Dm, nullptr, qkvp, nullptr, nullptr,
            Rows, 3*Dm, Dm);
        attn_kernel<<<gAtt, 256, ASMEM>>>(qkvp, ahi, alo);
        mm_gemm<1,false><<<gP, 256, GSMEM>>>(ahi, alo,
            apw + (size_t)l*Dm*Dm,
            attn_proj_b + (size_t)l*Dm, xp, xp, nullptr, nullptr,
            Rows, Dm, Dm);
        ln_kernel<<<Rows, 256>>>(xp, ln2_g + l*Dm, ln2_b + l*Dm, hhi, hlo);
        mm_gemm<2,false><<<gF, 256, GSMEM>>>(hhi, hlo,
            fcw + (size_t)l*Fm*Dm,
            fc_b + (size_t)l*Fm, nullptr, nullptr, fchi, fclo,
            Rows, Fm, Dm);
        mm_gemm<1,false><<<gP, 256, GSMEM>>>(fchi, fclo,
            mpw + (size_t)l*Dm*Fm,
            mlp_proj_b + (size_t)l*Dm, xp, xp, nullptr, nullptr,
            Rows, Dm, Fm);
    }

    ln_kernel<<<Rows, 256>>>(xp, lnf_g, lnf_b, hhi, hlo);
    mm_gemm<3,true><<<gV, 256, GSMEM>>>(hhi, hlo, tew,
        nullptr, nullptr, out, nullptr, nullptr,
        Rows, Vv, Dm);
}